// round 7
// baseline (speedup 1.0000x reference)
#include <cuda_runtime.h>
#include <cuda_fp16.h>
#include <cstdint>

#define T_FR 21
#define HH   30
#define WW   52
#define HWD  1560
#define L1T  32760
#define L2A  162
#define NH   12
#define HD   128
#define CDIM 1536
#define SKV  16
#define NKV  336   // 21*16

// ---------------- scratch (no allocations allowed) ----------------
__device__ float  g_buf1[(size_t)L1T * CDIM];   // Q proj (raw, f32)
__device__ __half g_bufh[(size_t)L1T * CDIM];   // fp16 qh, later fp16 attention out
__device__ __half g_kvw [NKV * CDIM];           // gathered fp16 kv window
__device__ float  g_k   [NKV * CDIM];
__device__ float  g_v   [NKV * CDIM];
__device__ float  g_heat[L1T];
__device__ float  g_qss [(size_t)L1T * 24];     // per-row partial sum-of-squares (6 bn * 4 chunks)
__device__ __half g_w   [(size_t)4 * CDIM * CDIM];  // fp16 Wq, Wk, Wv, Wo

// ---------------- small helpers ----------------
__device__ __forceinline__ float blockReduceSum256(float v, float* s8) {
    int lane = threadIdx.x & 31, warp = threadIdx.x >> 5;
#pragma unroll
    for (int o = 16; o; o >>= 1) v += __shfl_xor_sync(0xffffffffu, v, o);
    if (lane == 0) s8[warp] = v;
    __syncthreads();
    float t = 0.f;
#pragma unroll
    for (int i = 0; i < 8; i++) t += s8[i];
    __syncthreads();
    return t;
}

__device__ __forceinline__ uint32_t smem_u32(const void* p) {
    uint32_t a;
    asm("{ .reg .u64 t; cvta.to.shared.u64 t, %1; cvt.u32.u64 %0, t; }" : "=r"(a) : "l"(p));
    return a;
}
__device__ __forceinline__ void cpa16(uint32_t s, const void* g) {
    asm volatile("cp.async.cg.shared.global [%0], [%1], 16;" :: "r"(s), "l"(g));
}
__device__ __forceinline__ void cpa_commit() {
    asm volatile("cp.async.commit_group;" ::: "memory");
}
__device__ __forceinline__ void ldsm4(uint32_t* r, uint32_t a) {
    asm volatile("ldmatrix.sync.aligned.m8n8.x4.shared.b16 {%0,%1,%2,%3}, [%4];"
                 : "=r"(r[0]), "=r"(r[1]), "=r"(r[2]), "=r"(r[3]) : "r"(a));
}
__device__ __forceinline__ void mma_f16(float* c, const uint32_t* a, uint32_t b0, uint32_t b1) {
    asm volatile(
        "mma.sync.aligned.m16n8k16.row.col.f32.f16.f16.f32 "
        "{%0,%1,%2,%3}, {%4,%5,%6,%7}, {%8,%9}, {%0,%1,%2,%3};\n"
        : "+f"(c[0]), "+f"(c[1]), "+f"(c[2]), "+f"(c[3])
        : "r"(a[0]), "r"(a[1]), "r"(a[2]), "r"(a[3]), "r"(b0), "r"(b1));
}

#define SWZ(x) ((x) ^ (((x) >> 3) & 0x70))

// ---------------- heat + fp16 qh ----------------
__global__ void heat_kernel(const float* __restrict__ x, const float* __restrict__ te,
                            const float* __restrict__ mod, const float* __restrict__ Wh,
                            const float* __restrict__ bh) {
    __shared__ float s8[8];
    int row = blockIdx.x;
    const float* xr = x  + (size_t)row * CDIM;
    const float* tr = te + (size_t)row * CDIM;
    __half* rq = g_bufh + (size_t)row * CDIM;
    float xv[6], tv[6];
    float sum = 0.f, sq = 0.f;
#pragma unroll
    for (int i = 0; i < 6; i++) {
        int c = threadIdx.x + i * 256;
        xv[i] = xr[c]; tv[i] = tr[c];
        rq[c] = __float2half_rn(xv[i]);   // fp16 qh for the Q GEMM
        sum += xv[i]; sq += xv[i] * xv[i];
    }
    sum = blockReduceSum256(sum, s8);
    sq  = blockReduceSum256(sq,  s8);
    float mu  = sum * (1.f / CDIM);
    float var = sq * (1.f / CDIM) - mu * mu;
    float rs  = rsqrtf(var + 1e-6f);
    float dot = 0.f;
#pragma unroll
    for (int i = 0; i < 6; i++) {
        int c = threadIdx.x + i * 256;
        float ln = (xv[i] - mu) * rs;
        float y  = ln * (1.f + mod[CDIM + c] + tv[i]) + mod[c] + tv[i];
        dot += y * Wh[c];
    }
    dot = blockReduceSum256(dot, s8);
    if (threadIdx.x == 0)
        g_heat[row] = 1.f / (1.f + __expf(-(dot + bh[0])));
}

// ---------------- weights -> fp16 ----------------
__global__ void round_w(const float* __restrict__ Wq, const float* __restrict__ Wk,
                        const float* __restrict__ Wv, const float* __restrict__ Wo) {
    size_t t = (size_t)blockIdx.x * 256 + threadIdx.x;
    const size_t n4 = (size_t)CDIM * CDIM / 4;
    if (t >= n4) return;
    const float4* src[4] = {(const float4*)Wq, (const float4*)Wk,
                            (const float4*)Wv, (const float4*)Wo};
    __half2* dst = (__half2*)g_w;
#pragma unroll
    for (int m = 0; m < 4; m++) {
        float4 a = src[m][t];
        dst[m * n4 * 2 + t * 2 + 0] = __floats2half2_rn(a.x, a.y);
        dst[m * n4 * 2 + t * 2 + 1] = __floats2half2_rn(a.z, a.w);
    }
}

// ---------------- kv window gather (fp16) ----------------
__device__ __forceinline__ int audio_index(int b, int j) {
    int v = (b == 0) ? (-11 + j) : (8 * b - 10 + j);
    v = v < 0 ? 0 : v;
    return v > (L2A - 1) ? (L2A - 1) : v;
}

__global__ void gather_kvw(const float* __restrict__ kv) {
    int t = blockIdx.x * blockDim.x + threadIdx.x;
    const int C4 = CDIM / 4;
    if (t >= NKV * C4) return;
    int r = t / C4, c4 = t % C4;
    int b = r / SKV, s = r % SKV;
    int src = audio_index(b, s);
    float4 v = ((const float4*)kv)[(size_t)src * C4 + c4];
    __half2* dst = (__half2*)g_kvw;
    dst[((size_t)r * C4 + c4) * 2 + 0] = __floats2half2_rn(v.x, v.y);
    dst[((size_t)r * C4 + c4) * 2 + 1] = __floats2half2_rn(v.z, v.w);
}

// =====================================================================
// FP16 mma.sync GEMM, C[m][n] = sum_k A[m][k]*B[n][k] + bias[n]
// CTA tile 128(M) x 256(N), BK=64 (128B rows), 3-stage cp.async.
// 512 threads, 2(M) x 8(N) warp grid, 64x32 warp tiles, ldmatrix.x4.
// Optional qss: per-(row, bn*4+chunk) sum-of-squares for downstream RMS.
// =====================================================================
#define GBM 128
#define GBN 256
#define GBK 64
#define GTHR 512
#define A_STG 16384                       // 128 rows * 128 B
#define B_STG 32768                       // 256 rows * 128 B
#define STG_BYTES (A_STG + B_STG)         // 49152
#define NSTAGE 3
#define GSMEM_TOTAL (STG_BYTES * NSTAGE)  // 147456 B
#define NKT (CDIM / GBK)                  // 24
#define ESTRIDE 68                        // epilogue smem row stride (floats)

__global__ __launch_bounds__(GTHR, 1)
void gemm_tc(const __half* __restrict__ A, const __half* __restrict__ B,
             const float* __restrict__ bias, float* __restrict__ C, int M,
             float* __restrict__ qss)
{
    extern __shared__ float smem[];
    uint32_t sb = smem_u32(smem);
    const int tid = threadIdx.x;
    const int wid = tid >> 5, lane = tid & 31;
    const int wm = wid & 1, wn = wid >> 1;     // 2(M) x 8(N) warp grid
    const int bm = blockIdx.x, bn = blockIdx.y;

    // ldmatrix per-lane address components
    const int a_row = (lane & 7) + ((lane >> 3) & 1) * 8;
    const int a_kh  = (lane >> 4) * 16;
    const int b_row = (lane & 7) + (lane >> 4) * 8;
    const int b_kh  = ((lane >> 3) & 1) * 16;

    float acc[4][4][4];
#pragma unroll
    for (int mt = 0; mt < 4; mt++)
#pragma unroll
        for (int nt = 0; nt < 4; nt++)
#pragma unroll
            for (int i = 0; i < 4; i++) acc[mt][nt][i] = 0.f;

    // per stage: A 1024 chunks -> 2/thread; B 2048 -> 4/thread
#define LOAD_STAGE(sidx, ktile) do {                                             \
        uint32_t base_ = sb + (uint32_t)(sidx) * STG_BYTES;                      \
        int kc_ = (ktile) * GBK;                                                 \
        _Pragma("unroll")                                                        \
        for (int i_ = 0; i_ < 2; i_++) {                                         \
            int idx_ = i_ * GTHR + tid;                                          \
            int row_ = idx_ >> 3, c_ = idx_ & 7;                                 \
            int gr_ = bm * GBM + row_; gr_ = gr_ < M ? gr_ : M - 1;              \
            cpa16(base_ + SWZ(row_ * 128 + c_ * 16),                             \
                  A + (size_t)gr_ * CDIM + kc_ + c_ * 8);                        \
        }                                                                        \
        _Pragma("unroll")                                                        \
        for (int i_ = 0; i_ < 4; i_++) {                                         \
            int idx_ = i_ * GTHR + tid;                                          \
            int row_ = idx_ >> 3, c_ = idx_ & 7;                                 \
            cpa16(base_ + A_STG + SWZ(row_ * 128 + c_ * 16),                     \
                  B + (size_t)(bn * GBN + row_) * CDIM + kc_ + c_ * 8);          \
        }                                                                        \
        cpa_commit();                                                            \
    } while (0)

    LOAD_STAGE(0, 0);
    LOAD_STAGE(1, 1);

#pragma unroll 1
    for (int kt = 0; kt < NKT; kt++) {
        if (kt < NKT - 1) asm volatile("cp.async.wait_group 1;" ::: "memory");
        else              asm volatile("cp.async.wait_group 0;" ::: "memory");
        __syncthreads();
        if (kt + 2 < NKT) LOAD_STAGE((kt + 2) % NSTAGE, kt + 2);

        uint32_t As = sb + (kt % NSTAGE) * STG_BYTES;
        uint32_t Bs = As + A_STG;
#pragma unroll
        for (int ks = 0; ks < 4; ks++) {          // four k16 steps
            int kb = ks * 32;
            uint32_t af[4][4];
#pragma unroll
            for (int mt = 0; mt < 4; mt++)
                ldsm4(af[mt], As + SWZ((wm * 64 + mt * 16 + a_row) * 128 + kb + a_kh));
            uint32_t bf[2][4];
#pragma unroll
            for (int nt = 0; nt < 2; nt++)
                ldsm4(bf[nt], Bs + SWZ((wn * 32 + nt * 16 + b_row) * 128 + kb + b_kh));
#pragma unroll
            for (int nt = 0; nt < 2; nt++)
#pragma unroll
                for (int mt = 0; mt < 4; mt++) {
                    mma_f16(acc[mt][2 * nt],     af[mt], bf[nt][0], bf[nt][1]);
                    mma_f16(acc[mt][2 * nt + 1], af[mt], bf[nt][2], bf[nt][3]);
                }
        }
    }
    __syncthreads();

    // ---- epilogue: stage 128x64 column-chunks through smem, coalesced stores ----
    const int gid = lane >> 2, tig = lane & 3;
    float* es = smem;   // [128][ESTRIDE]
#pragma unroll 1
    for (int c = 0; c < 4; c++) {
        if ((wn >> 1) == c) {
            int colbase = (wn & 1) * 32;
#pragma unroll
            for (int mt = 0; mt < 4; mt++) {
#pragma unroll
                for (int nt = 0; nt < 4; nt++) {
                    int row = wm * 64 + mt * 16 + gid;
                    int col = colbase + nt * 8 + tig * 2;
                    *(float2*)&es[row * ESTRIDE + col] =
                        make_float2(acc[mt][nt][0], acc[mt][nt][1]);
                    *(float2*)&es[(row + 8) * ESTRIDE + col] =
                        make_float2(acc[mt][nt][2], acc[mt][nt][3]);
                }
            }
        }
        __syncthreads();
#pragma unroll
        for (int it = 0; it < 4; it++) {
            int idx = it * GTHR + tid;
            int row = idx >> 4, c4 = idx & 15;
            int gr = bm * GBM + row;
            float ssv = 0.f;
            if (gr < M) {
                int gc = bn * GBN + c * 64 + c4 * 4;
                const float* ep = &es[row * ESTRIDE + c4 * 4];
                float4 o;
                o.x = ep[0] + bias[gc + 0];
                o.y = ep[1] + bias[gc + 1];
                o.z = ep[2] + bias[gc + 2];
                o.w = ep[3] + bias[gc + 3];
                *(float4*)(C + (size_t)gr * CDIM + gc) = o;
                ssv = o.x * o.x + o.y * o.y + o.z * o.z + o.w * o.w;
            }
            if (qss) {
                // reduce the 16 lanes that share this row (consecutive tids)
#pragma unroll
                for (int off = 8; off; off >>= 1)
                    ssv += __shfl_xor_sync(0xffffffffu, ssv, off);
                if ((tid & 15) == 0 && gr < M)
                    qss[(size_t)gr * 24 + bn * 4 + c] = ssv;
            }
        }
        __syncthreads();
    }
#undef LOAD_STAGE
}

// ---------------- K rms + rope (in-place on g_k) ----------------
__global__ void k_rmsrope_kernel(const float* __restrict__ gkw, const float* __restrict__ kf) {
    __shared__ float s8[8];
    int row = blockIdx.x;
    float* base = g_k + (size_t)row * CDIM;
    float xr[3], xi[3];
    float sq = 0.f;
#pragma unroll
    for (int i = 0; i < 3; i++) {
        int p = threadIdx.x + i * 256;
        float2 v = ((float2*)base)[p];
        xr[i] = v.x; xi[i] = v.y;
        sq += v.x * v.x + v.y * v.y;
    }
    sq = blockReduceSum256(sq, s8);
    float rs = rsqrtf(sq * (1.f / CDIM) + 1e-6f);
    int s = row % SKV;
#pragma unroll
    for (int i = 0; i < 3; i++) {
        int p = threadIdx.x + i * 256;
        int j = p & 63;
        int pos = (j < 22) ? s : 0;
        float cs = kf[pos * 128 + 2 * j];
        float sn = kf[pos * 128 + 2 * j + 1];
        float ar = xr[i] * rs * gkw[2 * p];
        float ai = xi[i] * rs * gkw[2 * p + 1];
        ((float2*)base)[p] = make_float2(ar * cs - ai * sn, ar * sn + ai * cs);
    }
}

// ---------------- attention (fused Q rms+rope): softmax(QK^T/sqrt(128)) V * heat -> fp16 ----
__global__ __launch_bounds__(256) void attn_kernel(const float* __restrict__ gqw,
                                                   const float* __restrict__ qf) {
    __shared__ float ks[SKV][HD];
    __shared__ float vs[SKV][HD];
    int b = blockIdx.z, head = blockIdx.y, row0 = blockIdx.x * 64;
    for (int t = threadIdx.x; t < SKV * HD; t += 256) {
        int s = t >> 7, d = t & 127;
        size_t off = (size_t)(b * SKV + s) * CDIM + head * HD + d;
        ks[s][d] = g_k[off];
        vs[s][d] = g_v[off];
    }
    __syncthreads();
    int warp = threadIdx.x >> 5, lane = threadIdx.x & 31;
    // per-lane gq slice and rope j-indices (fixed per block)
    const float4 gq4 = *(const float4*)(gqw + head * HD + lane * 4);
    const int j0 = lane * 2, j1 = lane * 2 + 1;
#pragma unroll 1
    for (int r = 0; r < 8; r++) {
        int row = row0 + warp * 8 + r;
        if (row >= HWD) break;
        int grow = b * HWD + row;
        // row rms from GEMM-epilogue partials
        float ssum = 0.f;
        const float* qp = g_qss + (size_t)grow * 24;
#pragma unroll
        for (int i = 0; i < 24; i++) ssum += qp[i];
        float rs = rsqrtf(ssum * (1.f / CDIM) + 1e-6f);
        // rope freqs for this row
        int h = row / WW, w = row % WW;
        int pos0 = (j0 < 22) ? 0 : ((j0 < 43) ? h : w);
        int pos1 = (j1 < 22) ? 0 : ((j1 < 43) ? h : w);
        float cs0 = qf[pos0 * 128 + 2 * j0], sn0 = qf[pos0 * 128 + 2 * j0 + 1];
        float cs1 = qf[pos1 * 128 + 2 * j1], sn1 = qf[pos1 * 128 + 2 * j1 + 1];
        // load raw Q projection, apply rms * gq, rope
        float4 q4 = *(const float4*)(g_buf1 + (size_t)grow * CDIM + head * HD + lane * 4);
        float ax = q4.x * rs * gq4.x, ay = q4.y * rs * gq4.y;
        float az = q4.z * rs * gq4.z, aw = q4.w * rs * gq4.w;
        q4.x = ax * cs0 - ay * sn0; q4.y = ax * sn0 + ay * cs0;
        q4.z = az * cs1 - aw * sn1; q4.w = az * sn1 + aw * cs1;
        float sc[16];
#pragma unroll
        for (int s = 0; s < 16; s++) {
            float4 k4 = *(float4*)&ks[s][lane * 4];
            sc[s] = q4.x * k4.x + q4.y * k4.y + q4.z * k4.z + q4.w * k4.w;
        }
#pragma unroll
        for (int o = 16; o; o >>= 1)
#pragma unroll
            for (int s = 0; s < 16; s++)
                sc[s] += __shfl_xor_sync(0xffffffffu, sc[s], o);
        float m = -1e30f;
#pragma unroll
        for (int s = 0; s < 16; s++) {
            sc[s] *= 0.08838834764831843f;  // 1/sqrt(128)
            m = fmaxf(m, sc[s]);
        }
        float sum = 0.f;
#pragma unroll
        for (int s = 0; s < 16; s++) { sc[s] = __expf(sc[s] - m); sum += sc[s]; }
        float scale = g_heat[grow] / sum;
        float ox = 0.f, oy = 0.f, oz = 0.f, ow = 0.f;
#pragma unroll
        for (int s = 0; s < 16; s++) {
            float4 v4 = *(float4*)&vs[s][lane * 4];
            ox += sc[s] * v4.x; oy += sc[s] * v4.y;
            oz += sc[s] * v4.z; ow += sc[s] * v4.w;
        }
        __half2* dst = (__half2*)(g_bufh + (size_t)grow * CDIM + head * HD + lane * 4);
        dst[0] = __floats2half2_rn(ox * scale, oy * scale);
        dst[1] = __floats2half2_rn(oz * scale, ow * scale);
    }
}

// ---------------- launch ----------------
extern "C" void kernel_launch(void* const* d_in, const int* in_sizes, int n_in,
                              void* d_out, int out_size) {
    const float* qh  = (const float*)d_in[0];
    const float* kvh = (const float*)d_in[1];
    const float* te  = (const float*)d_in[2];
    const float* qf  = (const float*)d_in[4];
    const float* kvf = (const float*)d_in[5];
    const float* Wq  = (const float*)d_in[6];
    const float* bq  = (const float*)d_in[7];
    const float* Wk  = (const float*)d_in[8];
    const float* bk  = (const float*)d_in[9];
    const float* Wv  = (const float*)d_in[10];
    const float* bv  = (const float*)d_in[11];
    const float* Wo  = (const float*)d_in[12];
    const float* bo  = (const float*)d_in[13];
    const float* gqw = (const float*)d_in[14];
    const float* gkw = (const float*)d_in[15];
    const float* mod = (const float*)d_in[16];
    const float* Wh  = (const float*)d_in[17];
    const float* bh  = (const float*)d_in[18];
    float* out = (float*)d_out;

    float *buf1, *kbuf, *vbuf, *qss;
    __half *bufh, *kvw, *gw;
    cudaGetSymbolAddress((void**)&buf1, g_buf1);
    cudaGetSymbolAddress((void**)&bufh, g_bufh);
    cudaGetSymbolAddress((void**)&kvw,  g_kvw);
    cudaGetSymbolAddress((void**)&kbuf, g_k);
    cudaGetSymbolAddress((void**)&vbuf, g_v);
    cudaGetSymbolAddress((void**)&qss,  g_qss);
    cudaGetSymbolAddress((void**)&gw,   g_w);
    const size_t NW = (size_t)CDIM * CDIM;

    static bool attr_set = false;
    if (!attr_set) {
        cudaFuncSetAttribute(gemm_tc, cudaFuncAttributeMaxDynamicSharedMemorySize, GSMEM_TOTAL);
        attr_set = true;
    }

    heat_kernel<<<L1T, 256>>>(qh, te, mod, Wh, bh);          // g_heat + fp16 qh -> bufh
    round_w<<<(int)((NW / 4 + 255) / 256), 256>>>(Wq, Wk, Wv, Wo);
    gather_kvw<<<(NKV * (CDIM / 4) + 255) / 256, 256>>>(kvh);

    gemm_tc<<<dim3((L1T + GBM - 1) / GBM, CDIM / GBN), GTHR, GSMEM_TOTAL>>>(bufh, gw, bq, buf1, L1T, qss);
    gemm_tc<<<dim3((NKV + GBM - 1) / GBM, CDIM / GBN), GTHR, GSMEM_TOTAL>>>(kvw, gw + NW, bk, kbuf, NKV, nullptr);
    gemm_tc<<<dim3((NKV + GBM - 1) / GBM, CDIM / GBN), GTHR, GSMEM_TOTAL>>>(kvw, gw + 2 * NW, bv, vbuf, NKV, nullptr);

    k_rmsrope_kernel<<<NKV, 256>>>(gkw, kvf);

    attn_kernel<<<dim3((HWD + 63) / 64, NH, T_FR), 256>>>(gqw, qf);  // fp16 attn-out -> bufh

    gemm_tc<<<dim3((L1T + GBM - 1) / GBM, CDIM / GBN), GTHR, GSMEM_TOTAL>>>(bufh, gw + 3 * NW, bo, out, L1T, nullptr);
}

// round 9
// speedup vs baseline: 1.0047x; 1.0047x over previous
#include <cuda_runtime.h>
#include <cuda_fp16.h>
#include <cstdint>

#define T_FR 21
#define HH   30
#define WW   52
#define HWD  1560
#define L1T  32760
#define L2A  162
#define NH   12
#define HD   128
#define CDIM 1536
#define SKV  16
#define NKV  336   // 21*16

// ---------------- scratch (no allocations allowed) ----------------
__device__ __half g_qh  [(size_t)L1T * CDIM];   // Q proj (fp16, pre-RMS)
__device__ __half g_bufh[(size_t)L1T * CDIM];   // fp16 qh, later fp16 attention out
__device__ __half g_kvw [NKV * CDIM];           // gathered fp16 kv window
__device__ float  g_k   [NKV * CDIM];
__device__ float  g_v   [NKV * CDIM];
__device__ float  g_heat[L1T];
__device__ float  g_qss [(size_t)L1T * 24];     // per-row partial sum-of-squares (6 bn * 4 chunks)
__device__ __half g_w   [(size_t)4 * CDIM * CDIM];  // fp16 Wq, Wk, Wv, Wo

// ---------------- small helpers ----------------
__device__ __forceinline__ uint32_t smem_u32(const void* p) {
    uint32_t a;
    asm("{ .reg .u64 t; cvta.to.shared.u64 t, %1; cvt.u32.u64 %0, t; }" : "=r"(a) : "l"(p));
    return a;
}
__device__ __forceinline__ void cpa16(uint32_t s, const void* g) {
    asm volatile("cp.async.cg.shared.global [%0], [%1], 16;" :: "r"(s), "l"(g));
}
__device__ __forceinline__ void cpa_commit() {
    asm volatile("cp.async.commit_group;" ::: "memory");
}
__device__ __forceinline__ void ldsm4(uint32_t* r, uint32_t a) {
    asm volatile("ldmatrix.sync.aligned.m8n8.x4.shared.b16 {%0,%1,%2,%3}, [%4];"
                 : "=r"(r[0]), "=r"(r[1]), "=r"(r[2]), "=r"(r[3]) : "r"(a));
}
__device__ __forceinline__ void mma_f16(float* c, const uint32_t* a, uint32_t b0, uint32_t b1) {
    asm volatile(
        "mma.sync.aligned.m16n8k16.row.col.f32.f16.f16.f32 "
        "{%0,%1,%2,%3}, {%4,%5,%6,%7}, {%8,%9}, {%0,%1,%2,%3};\n"
        : "+f"(c[0]), "+f"(c[1]), "+f"(c[2]), "+f"(c[3])
        : "r"(a[0]), "r"(a[1]), "r"(a[2]), "r"(a[3]), "r"(b0), "r"(b1));
}

#define SWZ(x) ((x) ^ (((x) >> 3) & 0x70))

// ---------------- heat (warp-per-row, no smem/barriers) + fp16 qh ----------------
__global__ __launch_bounds__(256) void heat_kernel(
    const float* __restrict__ x, const float* __restrict__ te,
    const float* __restrict__ mod, const float* __restrict__ Wh,
    const float* __restrict__ bh)
{
    int warp = threadIdx.x >> 5, lane = threadIdx.x & 31;
    int row = blockIdx.x * 8 + warp;                 // 4095 * 8 = 32760 exactly
    const float2* xr = (const float2*)(x  + (size_t)row * CDIM);
    const float2* tr = (const float2*)(te + (size_t)row * CDIM);
    __half2* rq = (__half2*)(g_bufh + (size_t)row * CDIM);

    float2 xv[24], tv[24];
    float sum = 0.f, sq = 0.f;
#pragma unroll
    for (int j = 0; j < 24; j++) {
        int c2 = lane + j * 32;
        xv[j] = xr[c2]; tv[j] = tr[c2];
        rq[c2] = __floats2half2_rn(xv[j].x, xv[j].y);
        sum += xv[j].x + xv[j].y;
        sq  += xv[j].x * xv[j].x + xv[j].y * xv[j].y;
    }
#pragma unroll
    for (int o = 16; o; o >>= 1) {
        sum += __shfl_xor_sync(0xffffffffu, sum, o);
        sq  += __shfl_xor_sync(0xffffffffu, sq,  o);
    }
    float mu  = sum * (1.f / CDIM);
    float var = sq * (1.f / CDIM) - mu * mu;
    float rs  = rsqrtf(var + 1e-6f);

    const float2* mod0 = (const float2*)mod;
    const float2* mod1 = (const float2*)(mod + CDIM);
    const float2* wh2  = (const float2*)Wh;
    float dot = 0.f;
#pragma unroll
    for (int j = 0; j < 24; j++) {
        int c2 = lane + j * 32;
        float2 m0 = mod0[c2], m1 = mod1[c2], wv = wh2[c2];
        float ln0 = (xv[j].x - mu) * rs, ln1 = (xv[j].y - mu) * rs;
        float y0 = ln0 * (1.f + m1.x + tv[j].x) + m0.x + tv[j].x;
        float y1 = ln1 * (1.f + m1.y + tv[j].y) + m0.y + tv[j].y;
        dot += y0 * wv.x + y1 * wv.y;
    }
#pragma unroll
    for (int o = 16; o; o >>= 1) dot += __shfl_xor_sync(0xffffffffu, dot, o);
    if (lane == 0)
        g_heat[row] = 1.f / (1.f + __expf(-(dot + bh[0])));
}

// ---------------- weights -> fp16 ----------------
__global__ void round_w(const float* __restrict__ Wq, const float* __restrict__ Wk,
                        const float* __restrict__ Wv, const float* __restrict__ Wo) {
    size_t t = (size_t)blockIdx.x * 256 + threadIdx.x;
    const size_t n4 = (size_t)CDIM * CDIM / 4;
    if (t >= n4) return;
    const float4* src[4] = {(const float4*)Wq, (const float4*)Wk,
                            (const float4*)Wv, (const float4*)Wo};
    __half2* dst = (__half2*)g_w;
#pragma unroll
    for (int m = 0; m < 4; m++) {
        float4 a = src[m][t];
        dst[m * n4 * 2 + t * 2 + 0] = __floats2half2_rn(a.x, a.y);
        dst[m * n4 * 2 + t * 2 + 1] = __floats2half2_rn(a.z, a.w);
    }
}

// ---------------- kv window gather (fp16) ----------------
__device__ __forceinline__ int audio_index(int b, int j) {
    int v = (b == 0) ? (-11 + j) : (8 * b - 10 + j);
    v = v < 0 ? 0 : v;
    return v > (L2A - 1) ? (L2A - 1) : v;
}

__global__ void gather_kvw(const float* __restrict__ kv) {
    int t = blockIdx.x * blockDim.x + threadIdx.x;
    const int C4 = CDIM / 4;
    if (t >= NKV * C4) return;
    int r = t / C4, c4 = t % C4;
    int b = r / SKV, s = r % SKV;
    int src = audio_index(b, s);
    float4 v = ((const float4*)kv)[(size_t)src * C4 + c4];
    __half2* dst = (__half2*)g_kvw;
    dst[((size_t)r * C4 + c4) * 2 + 0] = __floats2half2_rn(v.x, v.y);
    dst[((size_t)r * C4 + c4) * 2 + 1] = __floats2half2_rn(v.z, v.w);
}

// =====================================================================
// FP16 mma.sync GEMM, C[m][n] = sum_k A[m][k]*B[n][k] + bias[n]
// CTA tile 128(M) x 256(N), BK=64 (128B rows), 3-stage cp.async.
// 256 threads, 2(M) x 4(N) warp grid, 64x64 warp tiles, ldmatrix.x4.
// Ch != null -> fp16 output (+ optional qss row sum-of-squares partials).
// =====================================================================
#define GBM 128
#define GBN 256
#define GBK 64
#define GTHR 256
#define A_STG 16384                       // 128 rows * 128 B
#define B_STG 32768                       // 256 rows * 128 B
#define STG_BYTES (A_STG + B_STG)         // 49152
#define NSTAGE 3
#define GSMEM_TOTAL (STG_BYTES * NSTAGE)  // 147456 B
#define NKT (CDIM / GBK)                  // 24
#define ESTRIDE 68                        // epilogue smem row stride (floats)

__global__ __launch_bounds__(GTHR, 1)
void gemm_tc(const __half* __restrict__ A, const __half* __restrict__ B,
             const float* __restrict__ bias, float* __restrict__ C,
             __half* __restrict__ Ch, int M, float* __restrict__ qss)
{
    extern __shared__ float smem[];
    uint32_t sb = smem_u32(smem);
    const int tid = threadIdx.x;
    const int wid = tid >> 5, lane = tid & 31;
    const int wm = wid & 1, wn = wid >> 1;     // 2(M) x 4(N) warp grid
    const int bm = blockIdx.x, bn = blockIdx.y;

    const int a_row = (lane & 7) + ((lane >> 3) & 1) * 8;
    const int a_kh  = (lane >> 4) * 16;
    const int b_row = (lane & 7) + (lane >> 4) * 8;
    const int b_kh  = ((lane >> 3) & 1) * 16;

    float acc[4][8][4];
#pragma unroll
    for (int mt = 0; mt < 4; mt++)
#pragma unroll
        for (int nt = 0; nt < 8; nt++)
#pragma unroll
            for (int i = 0; i < 4; i++) acc[mt][nt][i] = 0.f;

#define LOAD_STAGE(sidx, ktile) do {                                             \
        uint32_t base_ = sb + (uint32_t)(sidx) * STG_BYTES;                      \
        int kc_ = (ktile) * GBK;                                                 \
        _Pragma("unroll")                                                        \
        for (int i_ = 0; i_ < 4; i_++) {                                         \
            int idx_ = i_ * GTHR + tid;                                          \
            int row_ = idx_ >> 3, c_ = idx_ & 7;                                 \
            int gr_ = bm * GBM + row_; gr_ = gr_ < M ? gr_ : M - 1;              \
            cpa16(base_ + SWZ(row_ * 128 + c_ * 16),                             \
                  A + (size_t)gr_ * CDIM + kc_ + c_ * 8);                        \
        }                                                                        \
        _Pragma("unroll")                                                        \
        for (int i_ = 0; i_ < 8; i_++) {                                         \
            int idx_ = i_ * GTHR + tid;                                          \
            int row_ = idx_ >> 3, c_ = idx_ & 7;                                 \
            cpa16(base_ + A_STG + SWZ(row_ * 128 + c_ * 16),                     \
                  B + (size_t)(bn * GBN + row_) * CDIM + kc_ + c_ * 8);          \
        }                                                                        \
        cpa_commit();                                                            \
    } while (0)

    LOAD_STAGE(0, 0);
    LOAD_STAGE(1, 1);

#pragma unroll 1
    for (int kt = 0; kt < NKT; kt++) {
        if (kt < NKT - 1) asm volatile("cp.async.wait_group 1;" ::: "memory");
        else              asm volatile("cp.async.wait_group 0;" ::: "memory");
        __syncthreads();
        if (kt + 2 < NKT) LOAD_STAGE((kt + 2) % NSTAGE, kt + 2);

        uint32_t As = sb + (kt % NSTAGE) * STG_BYTES;
        uint32_t Bs = As + A_STG;
#pragma unroll
        for (int ks = 0; ks < 4; ks++) {          // four k16 steps
            int kb = ks * 32;
            uint32_t af[4][4];
#pragma unroll
            for (int mt = 0; mt < 4; mt++)
                ldsm4(af[mt], As + SWZ((wm * 64 + mt * 16 + a_row) * 128 + kb + a_kh));
            uint32_t bf[4][4];
#pragma unroll
            for (int nt = 0; nt < 4; nt++)
                ldsm4(bf[nt], Bs + SWZ((wn * 64 + nt * 16 + b_row) * 128 + kb + b_kh));
#pragma unroll
            for (int nt = 0; nt < 4; nt++)
#pragma unroll
                for (int mt = 0; mt < 4; mt++) {
                    mma_f16(acc[mt][2 * nt],     af[mt], bf[nt][0], bf[nt][1]);
                    mma_f16(acc[mt][2 * nt + 1], af[mt], bf[nt][2], bf[nt][3]);
                }
        }
    }
    __syncthreads();

    // ---- epilogue: stage 128x64 column-chunks through smem, coalesced stores ----
    const int gid = lane >> 2, tig = lane & 3;
    float* es = smem;   // [128][ESTRIDE]
#pragma unroll 1
    for (int c = 0; c < 4; c++) {
        if (wn == c) {
#pragma unroll
            for (int mt = 0; mt < 4; mt++) {
#pragma unroll
                for (int nt = 0; nt < 8; nt++) {
                    int row = wm * 64 + mt * 16 + gid;
                    int col = nt * 8 + tig * 2;
                    *(float2*)&es[row * ESTRIDE + col] =
                        make_float2(acc[mt][nt][0], acc[mt][nt][1]);
                    *(float2*)&es[(row + 8) * ESTRIDE + col] =
                        make_float2(acc[mt][nt][2], acc[mt][nt][3]);
                }
            }
        }
        __syncthreads();
#pragma unroll
        for (int it = 0; it < 8; it++) {
            int idx = it * GTHR + tid;
            int row = idx >> 4, c4 = idx & 15;
            int gr = bm * GBM + row;
            float ssv = 0.f;
            if (gr < M) {
                int gc = bn * GBN + c * 64 + c4 * 4;
                const float* ep = &es[row * ESTRIDE + c4 * 4];
                float4 o;
                o.x = ep[0] + bias[gc + 0];
                o.y = ep[1] + bias[gc + 1];
                o.z = ep[2] + bias[gc + 2];
                o.w = ep[3] + bias[gc + 3];
                if (Ch) {
                    __half2 h0 = __floats2half2_rn(o.x, o.y);
                    __half2 h1 = __floats2half2_rn(o.z, o.w);
                    __half2* dp = (__half2*)(Ch + (size_t)gr * CDIM + gc);
                    dp[0] = h0; dp[1] = h1;
                } else {
                    *(float4*)(C + (size_t)gr * CDIM + gc) = o;
                }
                ssv = o.x * o.x + o.y * o.y + o.z * o.z + o.w * o.w;
            }
            if (qss) {
#pragma unroll
                for (int off = 8; off; off >>= 1)
                    ssv += __shfl_xor_sync(0xffffffffu, ssv, off);
                if ((tid & 15) == 0 && gr < M)
                    qss[(size_t)gr * 24 + bn * 4 + c] = ssv;
            }
        }
        __syncthreads();
    }
#undef LOAD_STAGE
}

// ---------------- K rms + rope (in-place on g_k) ----------------
__global__ void k_rmsrope_kernel(const float* __restrict__ gkw, const float* __restrict__ kf) {
    __shared__ float s8[8];
    int row = blockIdx.x;
    float* base = g_k + (size_t)row * CDIM;
    int lane = threadIdx.x & 31, warp = threadIdx.x >> 5;
    float xr[3], xi[3];
    float sq = 0.f;
#pragma unroll
    for (int i = 0; i < 3; i++) {
        int p = threadIdx.x + i * 256;
        float2 v = ((float2*)base)[p];
        xr[i] = v.x; xi[i] = v.y;
        sq += v.x * v.x + v.y * v.y;
    }
#pragma unroll
    for (int o = 16; o; o >>= 1) sq += __shfl_xor_sync(0xffffffffu, sq, o);
    if (lane == 0) s8[warp] = sq;
    __syncthreads();
    float t = 0.f;
#pragma unroll
    for (int i = 0; i < 8; i++) t += s8[i];
    float rs = rsqrtf(t * (1.f / CDIM) + 1e-6f);
    int s = row % SKV;
#pragma unroll
    for (int i = 0; i < 3; i++) {
        int p = threadIdx.x + i * 256;
        int j = p & 63;
        int pos = (j < 22) ? s : 0;
        float cs = kf[pos * 128 + 2 * j];
        float sn = kf[pos * 128 + 2 * j + 1];
        float ar = xr[i] * rs * gkw[2 * p];
        float ai = xi[i] * rs * gkw[2 * p + 1];
        ((float2*)base)[p] = make_float2(ar * cs - ai * sn, ar * sn + ai * cs);
    }
}

// ---------------- attention (fused Q rms+rope): softmax(QK^T/sqrt(128)) V * heat -> fp16 ----
__global__ __launch_bounds__(256) void attn_kernel(const float* __restrict__ gqw,
                                                   const float* __restrict__ qf) {
    __shared__ float ks[SKV][HD];
    __shared__ float vs[SKV][HD];
    int b = blockIdx.z, head = blockIdx.y, row0 = blockIdx.x * 64;
    for (int t = threadIdx.x; t < SKV * HD; t += 256) {
        int s = t >> 7, d = t & 127;
        size_t off = (size_t)(b * SKV + s) * CDIM + head * HD + d;
        ks[s][d] = g_k[off];
        vs[s][d] = g_v[off];
    }
    __syncthreads();
    int warp = threadIdx.x >> 5, lane = threadIdx.x & 31;
    const float4 gq4 = *(const float4*)(gqw + head * HD + lane * 4);
    const int j0 = lane * 2, j1 = lane * 2 + 1;
#pragma unroll 1
    for (int r = 0; r < 8; r++) {
        int row = row0 + warp * 8 + r;
        if (row >= HWD) break;
        int grow = b * HWD + row;
        float ssum = 0.f;
        const float* qp = g_qss + (size_t)grow * 24;
#pragma unroll
        for (int i = 0; i < 24; i++) ssum += qp[i];
        float rs = rsqrtf(ssum * (1.f / CDIM) + 1e-6f);
        int h = row / WW, w = row % WW;
        int pos0 = (j0 < 22) ? 0 : ((j0 < 43) ? h : w);
        int pos1 = (j1 < 22) ? 0 : ((j1 < 43) ? h : w);
        float cs0 = qf[pos0 * 128 + 2 * j0], sn0 = qf[pos0 * 128 + 2 * j0 + 1];
        float cs1 = qf[pos1 * 128 + 2 * j1], sn1 = qf[pos1 * 128 + 2 * j1 + 1];
        const __half2* qh2 = (const __half2*)(g_qh + (size_t)grow * CDIM + head * HD + lane * 4);
        float2 f0 = __half22float2(qh2[0]), f1 = __half22float2(qh2[1]);
        float ax = f0.x * rs * gq4.x, ay = f0.y * rs * gq4.y;
        float az = f1.x * rs * gq4.z, aw = f1.y * rs * gq4.w;
        float4 q4;
        q4.x = ax * cs0 - ay * sn0; q4.y = ax * sn0 + ay * cs0;
        q4.z = az * cs1 - aw * sn1; q4.w = az * sn1 + aw * cs1;
        float sc[16];
#pragma unroll
        for (int s = 0; s < 16; s++) {
            float4 k4 = *(float4*)&ks[s][lane * 4];
            sc[s] = q4.x * k4.x + q4.y * k4.y + q4.z * k4.z + q4.w * k4.w;
        }
#pragma unroll
        for (int o = 16; o; o >>= 1)
#pragma unroll
            for (int s = 0; s < 16; s++)
                sc[s] += __shfl_xor_sync(0xffffffffu, sc[s], o);
        float m = -1e30f;
#pragma unroll
        for (int s = 0; s < 16; s++) {
            sc[s] *= 0.08838834764831843f;  // 1/sqrt(128)
            m = fmaxf(m, sc[s]);
        }
        float sum = 0.f;
#pragma unroll
        for (int s = 0; s < 16; s++) { sc[s] = __expf(sc[s] - m); sum += sc[s]; }
        float scale = g_heat[grow] / sum;
        float ox = 0.f, oy = 0.f, oz = 0.f, ow = 0.f;
#pragma unroll
        for (int s = 0; s < 16; s++) {
            float4 v4 = *(float4*)&vs[s][lane * 4];
            ox += sc[s] * v4.x; oy += sc[s] * v4.y;
            oz += sc[s] * v4.z; ow += sc[s] * v4.w;
        }
        __half2* dst = (__half2*)(g_bufh + (size_t)grow * CDIM + head * HD + lane * 4);
        dst[0] = __floats2half2_rn(ox * scale, oy * scale);
        dst[1] = __floats2half2_rn(oz * scale, ow * scale);
    }
}

// ---------------- launch ----------------
extern "C" void kernel_launch(void* const* d_in, const int* in_sizes, int n_in,
                              void* d_out, int out_size) {
    const float* qh  = (const float*)d_in[0];
    const float* kvh = (const float*)d_in[1];
    const float* te  = (const float*)d_in[2];
    const float* qf  = (const float*)d_in[4];
    const float* kvf = (const float*)d_in[5];
    const float* Wq  = (const float*)d_in[6];
    const float* bq  = (const float*)d_in[7];
    const float* Wk  = (const float*)d_in[8];
    const float* bk  = (const float*)d_in[9];
    const float* Wv  = (const float*)d_in[10];
    const float* bv  = (const float*)d_in[11];
    const float* Wo  = (const float*)d_in[12];
    const float* bo  = (const float*)d_in[13];
    const float* gqw = (const float*)d_in[14];
    const float* gkw = (const float*)d_in[15];
    const float* mod = (const float*)d_in[16];
    const float* Wh  = (const float*)d_in[17];
    const float* bh  = (const float*)d_in[18];
    float* out = (float*)d_out;

    float *kbuf, *vbuf, *qss;
    __half *qhbuf, *bufh, *kvw, *gw;
    cudaGetSymbolAddress((void**)&qhbuf, g_qh);
    cudaGetSymbolAddress((void**)&bufh,  g_bufh);
    cudaGetSymbolAddress((void**)&kvw,   g_kvw);
    cudaGetSymbolAddress((void**)&kbuf,  g_k);
    cudaGetSymbolAddress((void**)&vbuf,  g_v);
    cudaGetSymbolAddress((void**)&qss,   g_qss);
    cudaGetSymbolAddress((void**)&gw,    g_w);
    const size_t NW = (size_t)CDIM * CDIM;

    static bool attr_set = false;
    if (!attr_set) {
        cudaFuncSetAttribute(gemm_tc, cudaFuncAttributeMaxDynamicSharedMemorySize, GSMEM_TOTAL);
        attr_set = true;
    }

    heat_kernel<<<L1T / 8, 256>>>(qh, te, mod, Wh, bh);      // g_heat + fp16 qh -> bufh
    round_w<<<(int)((NW / 4 + 255) / 256), 256>>>(Wq, Wk, Wv, Wo);
    gather_kvw<<<(NKV * (CDIM / 4) + 255) / 256, 256>>>(kvh);

    gemm_tc<<<dim3((L1T + GBM - 1) / GBM, CDIM / GBN), GTHR, GSMEM_TOTAL>>>(
        bufh, gw, bq, nullptr, qhbuf, L1T, qss);             // Q proj -> fp16 + qss
    gemm_tc<<<dim3((NKV + GBM - 1) / GBM, CDIM / GBN), GTHR, GSMEM_TOTAL>>>(
        kvw, gw + NW, bk, kbuf, nullptr, NKV, nullptr);
    gemm_tc<<<dim3((NKV + GBM - 1) / GBM, CDIM / GBN), GTHR, GSMEM_TOTAL>>>(
        kvw, gw + 2 * NW, bv, vbuf, nullptr, NKV, nullptr);

    k_rmsrope_kernel<<<NKV, 256>>>(gkw, kvf);

    attn_kernel<<<dim3((HWD + 63) / 64, NH, T_FR), 256>>>(gqw, qf);  // fp16 attn-out -> bufh

    gemm_tc<<<dim3((L1T + GBM - 1) / GBM, CDIM / GBN), GTHR, GSMEM_TOTAL>>>(
        bufh, gw + 3 * NW, bo, out, nullptr, L1T, nullptr);
}

// round 10
// speedup vs baseline: 1.0413x; 1.0364x over previous
#include <cuda_runtime.h>
#include <cuda_fp16.h>
#include <cstdint>

#define T_FR 21
#define HH   30
#define WW   52
#define HWD  1560
#define L1T  32760
#define L2A  162
#define NH   12
#define HD   128
#define CDIM 1536
#define SKV  16
#define NKV  336   // 21*16

// ---------------- scratch (no allocations allowed) ----------------
__device__ __half g_qh  [(size_t)L1T * CDIM];   // Q proj fp16 (rms+rope applied in place)
__device__ __half g_bufh[(size_t)L1T * CDIM];   // fp16 qh, later fp16 attention out
__device__ __half g_kvw [NKV * CDIM];           // gathered fp16 kv window
__device__ float  g_k   [NKV * CDIM];
__device__ float  g_v   [NKV * CDIM];
__device__ float  g_heat[L1T];
__device__ __half g_w   [(size_t)4 * CDIM * CDIM];  // fp16 Wq, Wk, Wv, Wo

// ---------------- small helpers ----------------
__device__ __forceinline__ float blockReduceSum256(float v, float* s8) {
    int lane = threadIdx.x & 31, warp = threadIdx.x >> 5;
#pragma unroll
    for (int o = 16; o; o >>= 1) v += __shfl_xor_sync(0xffffffffu, v, o);
    if (lane == 0) s8[warp] = v;
    __syncthreads();
    float t = 0.f;
#pragma unroll
    for (int i = 0; i < 8; i++) t += s8[i];
    __syncthreads();
    return t;
}

__device__ __forceinline__ uint32_t smem_u32(const void* p) {
    uint32_t a;
    asm("{ .reg .u64 t; cvta.to.shared.u64 t, %1; cvt.u32.u64 %0, t; }" : "=r"(a) : "l"(p));
    return a;
}
__device__ __forceinline__ void cpa16(uint32_t s, const void* g) {
    asm volatile("cp.async.cg.shared.global [%0], [%1], 16;" :: "r"(s), "l"(g));
}
__device__ __forceinline__ void cpa_commit() {
    asm volatile("cp.async.commit_group;" ::: "memory");
}
__device__ __forceinline__ void ldsm4(uint32_t* r, uint32_t a) {
    asm volatile("ldmatrix.sync.aligned.m8n8.x4.shared.b16 {%0,%1,%2,%3}, [%4];"
                 : "=r"(r[0]), "=r"(r[1]), "=r"(r[2]), "=r"(r[3]) : "r"(a));
}
__device__ __forceinline__ void mma_f16(float* c, const uint32_t* a, uint32_t b0, uint32_t b1) {
    asm volatile(
        "mma.sync.aligned.m16n8k16.row.col.f32.f16.f16.f32 "
        "{%0,%1,%2,%3}, {%4,%5,%6,%7}, {%8,%9}, {%0,%1,%2,%3};\n"
        : "+f"(c[0]), "+f"(c[1]), "+f"(c[2]), "+f"(c[3])
        : "r"(a[0]), "r"(a[1]), "r"(a[2]), "r"(a[3]), "r"(b0), "r"(b1));
}

#define SWZ(x) ((x) ^ (((x) >> 3) & 0x70))

// ---------------- heat (block-per-row, R6 layout) + fp16 qh ----------------
__global__ void heat_kernel(const float* __restrict__ x, const float* __restrict__ te,
                            const float* __restrict__ mod, const float* __restrict__ Wh,
                            const float* __restrict__ bh) {
    __shared__ float s8[8];
    int row = blockIdx.x;
    const float* xr = x  + (size_t)row * CDIM;
    const float* tr = te + (size_t)row * CDIM;
    __half* rq = g_bufh + (size_t)row * CDIM;
    float xv[6], tv[6];
    float sum = 0.f, sq = 0.f;
#pragma unroll
    for (int i = 0; i < 6; i++) {
        int c = threadIdx.x + i * 256;
        xv[i] = xr[c]; tv[i] = tr[c];
        rq[c] = __float2half_rn(xv[i]);   // fp16 qh for the Q GEMM
        sum += xv[i]; sq += xv[i] * xv[i];
    }
    sum = blockReduceSum256(sum, s8);
    sq  = blockReduceSum256(sq,  s8);
    float mu  = sum * (1.f / CDIM);
    float var = sq * (1.f / CDIM) - mu * mu;
    float rs  = rsqrtf(var + 1e-6f);
    float dot = 0.f;
#pragma unroll
    for (int i = 0; i < 6; i++) {
        int c = threadIdx.x + i * 256;
        float ln = (xv[i] - mu) * rs;
        float y  = ln * (1.f + mod[CDIM + c] + tv[i]) + mod[c] + tv[i];
        dot += y * Wh[c];
    }
    dot = blockReduceSum256(dot, s8);
    if (threadIdx.x == 0)
        g_heat[row] = 1.f / (1.f + __expf(-(dot + bh[0])));
}

// ---------------- weights -> fp16 ----------------
__global__ void round_w(const float* __restrict__ Wq, const float* __restrict__ Wk,
                        const float* __restrict__ Wv, const float* __restrict__ Wo) {
    size_t t = (size_t)blockIdx.x * 256 + threadIdx.x;
    const size_t n4 = (size_t)CDIM * CDIM / 4;
    if (t >= n4) return;
    const float4* src[4] = {(const float4*)Wq, (const float4*)Wk,
                            (const float4*)Wv, (const float4*)Wo};
    __half2* dst = (__half2*)g_w;
#pragma unroll
    for (int m = 0; m < 4; m++) {
        float4 a = src[m][t];
        dst[m * n4 * 2 + t * 2 + 0] = __floats2half2_rn(a.x, a.y);
        dst[m * n4 * 2 + t * 2 + 1] = __floats2half2_rn(a.z, a.w);
    }
}

// ---------------- kv window gather (fp16) ----------------
__device__ __forceinline__ int audio_index(int b, int j) {
    int v = (b == 0) ? (-11 + j) : (8 * b - 10 + j);
    v = v < 0 ? 0 : v;
    return v > (L2A - 1) ? (L2A - 1) : v;
}

__global__ void gather_kvw(const float* __restrict__ kv) {
    int t = blockIdx.x * blockDim.x + threadIdx.x;
    const int C4 = CDIM / 4;
    if (t >= NKV * C4) return;
    int r = t / C4, c4 = t % C4;
    int b = r / SKV, s = r % SKV;
    int src = audio_index(b, s);
    float4 v = ((const float4*)kv)[(size_t)src * C4 + c4];
    __half2* dst = (__half2*)g_kvw;
    dst[((size_t)r * C4 + c4) * 2 + 0] = __floats2half2_rn(v.x, v.y);
    dst[((size_t)r * C4 + c4) * 2 + 1] = __floats2half2_rn(v.z, v.w);
}

// =====================================================================
// FP16 mma.sync GEMM, C[m][n] = sum_k A[m][k]*B[n][k] + bias[n]
// CTA tile 128(M) x 256(N), BK=64 (128B rows), 3-stage cp.async.
// 256 threads, 2(M) x 4(N) warp grid, 64x64 warp tiles, ldmatrix.x4.
// ks-level fragment double-buffering hides ldsm latency behind mma.
// Ch != null -> fp16 output.
// =====================================================================
#define GBM 128
#define GBN 256
#define GBK 64
#define GTHR 256
#define A_STG 16384                       // 128 rows * 128 B
#define B_STG 32768                       // 256 rows * 128 B
#define STG_BYTES (A_STG + B_STG)         // 49152
#define NSTAGE 3
#define GSMEM_TOTAL (STG_BYTES * NSTAGE)  // 147456 B
#define NKT (CDIM / GBK)                  // 24
#define ESTRIDE 68                        // epilogue smem row stride (floats)

__global__ __launch_bounds__(GTHR, 1)
void gemm_tc(const __half* __restrict__ A, const __half* __restrict__ B,
             const float* __restrict__ bias, float* __restrict__ C,
             __half* __restrict__ Ch, int M)
{
    extern __shared__ float smem[];
    uint32_t sb = smem_u32(smem);
    const int tid = threadIdx.x;
    const int wid = tid >> 5, lane = tid & 31;
    const int wm = wid & 1, wn = wid >> 1;     // 2(M) x 4(N) warp grid
    const int bm = blockIdx.x, bn = blockIdx.y;

    const int a_row = (lane & 7) + ((lane >> 3) & 1) * 8;
    const int a_kh  = (lane >> 4) * 16;
    const int b_row = (lane & 7) + (lane >> 4) * 8;
    const int b_kh  = ((lane >> 3) & 1) * 16;

    float acc[4][8][4];
#pragma unroll
    for (int mt = 0; mt < 4; mt++)
#pragma unroll
        for (int nt = 0; nt < 8; nt++)
#pragma unroll
            for (int i = 0; i < 4; i++) acc[mt][nt][i] = 0.f;

#define LOAD_STAGE(sidx, ktile) do {                                             \
        uint32_t base_ = sb + (uint32_t)(sidx) * STG_BYTES;                      \
        int kc_ = (ktile) * GBK;                                                 \
        _Pragma("unroll")                                                        \
        for (int i_ = 0; i_ < 4; i_++) {                                         \
            int idx_ = i_ * GTHR + tid;                                          \
            int row_ = idx_ >> 3, c_ = idx_ & 7;                                 \
            int gr_ = bm * GBM + row_; gr_ = gr_ < M ? gr_ : M - 1;              \
            cpa16(base_ + SWZ(row_ * 128 + c_ * 16),                             \
                  A + (size_t)gr_ * CDIM + kc_ + c_ * 8);                        \
        }                                                                        \
        _Pragma("unroll")                                                        \
        for (int i_ = 0; i_ < 8; i_++) {                                         \
            int idx_ = i_ * GTHR + tid;                                          \
            int row_ = idx_ >> 3, c_ = idx_ & 7;                                 \
            cpa16(base_ + A_STG + SWZ(row_ * 128 + c_ * 16),                     \
                  B + (size_t)(bn * GBN + row_) * CDIM + kc_ + c_ * 8);          \
        }                                                                        \
        cpa_commit();                                                            \
    } while (0)

// load all 8 fragments of k16-step (kb = byte offset) into buffer slot s_
#define LDFRAGS(s_, kb_) do {                                                    \
        _Pragma("unroll")                                                        \
        for (int mt_ = 0; mt_ < 4; mt_++)                                        \
            ldsm4(af[s_][mt_], As + SWZ((wm * 64 + mt_ * 16 + a_row) * 128 + (kb_) + a_kh)); \
        _Pragma("unroll")                                                        \
        for (int nt_ = 0; nt_ < 4; nt_++)                                        \
            ldsm4(bf[s_][nt_], Bs + SWZ((wn * 64 + nt_ * 16 + b_row) * 128 + (kb_) + b_kh)); \
    } while (0)

    LOAD_STAGE(0, 0);
    LOAD_STAGE(1, 1);

#pragma unroll 1
    for (int kt = 0; kt < NKT; kt++) {
        if (kt < NKT - 1) asm volatile("cp.async.wait_group 1;" ::: "memory");
        else              asm volatile("cp.async.wait_group 0;" ::: "memory");
        __syncthreads();
        if (kt + 2 < NKT) LOAD_STAGE((kt + 2) % NSTAGE, kt + 2);

        uint32_t As = sb + (kt % NSTAGE) * STG_BYTES;
        uint32_t Bs = As + A_STG;
        uint32_t af[2][4][4], bf[2][4][4];
        LDFRAGS(0, 0);
#pragma unroll
        for (int ks = 0; ks < 4; ks++) {          // four k16 steps
            int cur = ks & 1;
            if (ks < 3) {
                int nb = (ks + 1) * 32;
                int nxt = cur ^ 1;
                LDFRAGS(nxt, nb);
            }
#pragma unroll
            for (int nt = 0; nt < 4; nt++)
#pragma unroll
                for (int mt = 0; mt < 4; mt++) {
                    mma_f16(acc[mt][2 * nt],     af[cur][mt], bf[cur][nt][0], bf[cur][nt][1]);
                    mma_f16(acc[mt][2 * nt + 1], af[cur][mt], bf[cur][nt][2], bf[cur][nt][3]);
                }
        }
    }
    __syncthreads();

    // ---- epilogue: stage 128x64 column-chunks through smem, coalesced stores ----
    const int gid = lane >> 2, tig = lane & 3;
    float* es = smem;   // [128][ESTRIDE]
#pragma unroll 1
    for (int c = 0; c < 4; c++) {
        if (wn == c) {
#pragma unroll
            for (int mt = 0; mt < 4; mt++) {
#pragma unroll
                for (int nt = 0; nt < 8; nt++) {
                    int row = wm * 64 + mt * 16 + gid;
                    int col = nt * 8 + tig * 2;
                    *(float2*)&es[row * ESTRIDE + col] =
                        make_float2(acc[mt][nt][0], acc[mt][nt][1]);
                    *(float2*)&es[(row + 8) * ESTRIDE + col] =
                        make_float2(acc[mt][nt][2], acc[mt][nt][3]);
                }
            }
        }
        __syncthreads();
#pragma unroll
        for (int it = 0; it < 8; it++) {
            int idx = it * GTHR + tid;
            int row = idx >> 4, c4 = idx & 15;
            int gr = bm * GBM + row;
            if (gr < M) {
                int gc = bn * GBN + c * 64 + c4 * 4;
                const float* ep = &es[row * ESTRIDE + c4 * 4];
                float4 o;
                o.x = ep[0] + bias[gc + 0];
                o.y = ep[1] + bias[gc + 1];
                o.z = ep[2] + bias[gc + 2];
                o.w = ep[3] + bias[gc + 3];
                if (Ch) {
                    __half2* dp = (__half2*)(Ch + (size_t)gr * CDIM + gc);
                    dp[0] = __floats2half2_rn(o.x, o.y);
                    dp[1] = __floats2half2_rn(o.z, o.w);
                } else {
                    *(float4*)(C + (size_t)gr * CDIM + gc) = o;
                }
            }
        }
        __syncthreads();
    }
#undef LOAD_STAGE
#undef LDFRAGS
}

// ---------------- Q rms + rope (in-place on fp16 g_qh) ----------------
__global__ void q_rmsrope_kernel(const float* __restrict__ gqw, const float* __restrict__ qf) {
    __shared__ float s8[8];
    int row = blockIdx.x;
    __half2* base = (__half2*)(g_qh + (size_t)row * CDIM);
    float2 v[3];
    float sq = 0.f;
#pragma unroll
    for (int i = 0; i < 3; i++) {
        int p = threadIdx.x + i * 256;
        v[i] = __half22float2(base[p]);
        sq += v[i].x * v[i].x + v[i].y * v[i].y;
    }
    sq = blockReduceSum256(sq, s8);
    float rs = rsqrtf(sq * (1.f / CDIM) + 1e-6f);
    int h = row % HWD / WW, w = row % WW;
#pragma unroll
    for (int i = 0; i < 3; i++) {
        int p = threadIdx.x + i * 256;
        int j = p & 63;
        int pos = (j < 22) ? 0 : ((j < 43) ? h : w);
        float cs = qf[pos * 128 + 2 * j];
        float sn = qf[pos * 128 + 2 * j + 1];
        float ar = v[i].x * rs * gqw[2 * p];
        float ai = v[i].y * rs * gqw[2 * p + 1];
        base[p] = __floats2half2_rn(ar * cs - ai * sn, ar * sn + ai * cs);
    }
}

// ---------------- K rms + rope (in-place on g_k) ----------------
__global__ void k_rmsrope_kernel(const float* __restrict__ gkw, const float* __restrict__ kf) {
    __shared__ float s8[8];
    int row = blockIdx.x;
    float* base = g_k + (size_t)row * CDIM;
    float xr[3], xi[3];
    float sq = 0.f;
#pragma unroll
    for (int i = 0; i < 3; i++) {
        int p = threadIdx.x + i * 256;
        float2 v = ((float2*)base)[p];
        xr[i] = v.x; xi[i] = v.y;
        sq += v.x * v.x + v.y * v.y;
    }
    sq = blockReduceSum256(sq, s8);
    float rs = rsqrtf(sq * (1.f / CDIM) + 1e-6f);
    int s = row % SKV;
#pragma unroll
    for (int i = 0; i < 3; i++) {
        int p = threadIdx.x + i * 256;
        int j = p & 63;
        int pos = (j < 22) ? s : 0;
        float cs = kf[pos * 128 + 2 * j];
        float sn = kf[pos * 128 + 2 * j + 1];
        float ar = xr[i] * rs * gkw[2 * p];
        float ai = xi[i] * rs * gkw[2 * p + 1];
        ((float2*)base)[p] = make_float2(ar * cs - ai * sn, ar * sn + ai * cs);
    }
}

// ---------------- attention: softmax(QK^T/sqrt(128)) V * heat -> fp16 ----------------
__global__ __launch_bounds__(256) void attn_kernel() {
    __shared__ float ks[SKV][HD];
    __shared__ float vs[SKV][HD];
    int b = blockIdx.z, head = blockIdx.y, row0 = blockIdx.x * 64;
    for (int t = threadIdx.x; t < SKV * HD; t += 256) {
        int s = t >> 7, d = t & 127;
        size_t off = (size_t)(b * SKV + s) * CDIM + head * HD + d;
        ks[s][d] = g_k[off];
        vs[s][d] = g_v[off];
    }
    __syncthreads();
    int warp = threadIdx.x >> 5, lane = threadIdx.x & 31;
#pragma unroll 1
    for (int r = 0; r < 8; r++) {
        int row = row0 + warp * 8 + r;
        if (row >= HWD) break;
        int grow = b * HWD + row;
        const __half2* qh2 = (const __half2*)(g_qh + (size_t)grow * CDIM + head * HD + lane * 4);
        float2 f0 = __half22float2(qh2[0]), f1 = __half22float2(qh2[1]);
        float4 q4 = make_float4(f0.x, f0.y, f1.x, f1.y);
        float sc[16];
#pragma unroll
        for (int s = 0; s < 16; s++) {
            float4 k4 = *(float4*)&ks[s][lane * 4];
            sc[s] = q4.x * k4.x + q4.y * k4.y + q4.z * k4.z + q4.w * k4.w;
        }
#pragma unroll
        for (int o = 16; o; o >>= 1)
#pragma unroll
            for (int s = 0; s < 16; s++)
                sc[s] += __shfl_xor_sync(0xffffffffu, sc[s], o);
        float m = -1e30f;
#pragma unroll
        for (int s = 0; s < 16; s++) {
            sc[s] *= 0.08838834764831843f;  // 1/sqrt(128)
            m = fmaxf(m, sc[s]);
        }
        float sum = 0.f;
#pragma unroll
        for (int s = 0; s < 16; s++) { sc[s] = __expf(sc[s] - m); sum += sc[s]; }
        float scale = g_heat[grow] / sum;
        float ox = 0.f, oy = 0.f, oz = 0.f, ow = 0.f;
#pragma unroll
        for (int s = 0; s < 16; s++) {
            float4 v4 = *(float4*)&vs[s][lane * 4];
            ox += sc[s] * v4.x; oy += sc[s] * v4.y;
            oz += sc[s] * v4.z; ow += sc[s] * v4.w;
        }
        __half2* dst = (__half2*)(g_bufh + (size_t)grow * CDIM + head * HD + lane * 4);
        dst[0] = __floats2half2_rn(ox * scale, oy * scale);
        dst[1] = __floats2half2_rn(oz * scale, ow * scale);
    }
}

// ---------------- launch ----------------
extern "C" void kernel_launch(void* const* d_in, const int* in_sizes, int n_in,
                              void* d_out, int out_size) {
    const float* qh  = (const float*)d_in[0];
    const float* kvh = (const float*)d_in[1];
    const float* te  = (const float*)d_in[2];
    const float* qf  = (const float*)d_in[4];
    const float* kvf = (const float*)d_in[5];
    const float* Wq  = (const float*)d_in[6];
    const float* bq  = (const float*)d_in[7];
    const float* Wk  = (const float*)d_in[8];
    const float* bk  = (const float*)d_in[9];
    const float* Wv  = (const float*)d_in[10];
    const float* bv  = (const float*)d_in[11];
    const float* Wo  = (const float*)d_in[12];
    const float* bo  = (const float*)d_in[13];
    const float* gqw = (const float*)d_in[14];
    const float* gkw = (const float*)d_in[15];
    const float* mod = (const float*)d_in[16];
    const float* Wh  = (const float*)d_in[17];
    const float* bh  = (const float*)d_in[18];
    float* out = (float*)d_out;

    float *kbuf, *vbuf;
    __half *qhbuf, *bufh, *kvw, *gw;
    cudaGetSymbolAddress((void**)&qhbuf, g_qh);
    cudaGetSymbolAddress((void**)&bufh,  g_bufh);
    cudaGetSymbolAddress((void**)&kvw,   g_kvw);
    cudaGetSymbolAddress((void**)&kbuf,  g_k);
    cudaGetSymbolAddress((void**)&vbuf,  g_v);
    cudaGetSymbolAddress((void**)&gw,    g_w);
    const size_t NW = (size_t)CDIM * CDIM;

    static bool attr_set = false;
    if (!attr_set) {
        cudaFuncSetAttribute(gemm_tc, cudaFuncAttributeMaxDynamicSharedMemorySize, GSMEM_TOTAL);
        attr_set = true;
    }

    heat_kernel<<<L1T, 256>>>(qh, te, mod, Wh, bh);          // g_heat + fp16 qh -> bufh
    round_w<<<(int)((NW / 4 + 255) / 256), 256>>>(Wq, Wk, Wv, Wo);
    gather_kvw<<<(NKV * (CDIM / 4) + 255) / 256, 256>>>(kvh);

    gemm_tc<<<dim3((L1T + GBM - 1) / GBM, CDIM / GBN), GTHR, GSMEM_TOTAL>>>(
        bufh, gw, bq, nullptr, qhbuf, L1T);                  // Q proj -> fp16 g_qh
    gemm_tc<<<dim3((NKV + GBM - 1) / GBM, CDIM / GBN), GTHR, GSMEM_TOTAL>>>(
        kvw, gw + NW, bk, kbuf, nullptr, NKV);
    gemm_tc<<<dim3((NKV + GBM - 1) / GBM, CDIM / GBN), GTHR, GSMEM_TOTAL>>>(
        kvw, gw + 2 * NW, bv, vbuf, nullptr, NKV);

    q_rmsrope_kernel<<<L1T, 256>>>(gqw, qf);                 // in-place fp16
    k_rmsrope_kernel<<<NKV, 256>>>(gkw, kvf);

    attn_kernel<<<dim3((HWD + 63) / 64, NH, T_FR), 256>>>(); // fp16 attn-out -> bufh

    gemm_tc<<<dim3((L1T + GBM - 1) / GBM, CDIM / GBN), GTHR, GSMEM_TOTAL>>>(
        bufh, gw + 3 * NW, bo, out, nullptr, L1T);
}

// round 13
// speedup vs baseline: 1.0622x; 1.0201x over previous
#include <cuda_runtime.h>
#include <cuda_fp16.h>
#include <cstdint>

#define T_FR 21
#define HH   30
#define WW   52
#define HWD  1560
#define L1T  32760
#define L2A  162
#define NH   12
#define HD   128
#define CDIM 1536
#define SKV  16
#define NKV  336   // 21*16

// ---------------- scratch (no allocations allowed) ----------------
__device__ __half g_qh  [(size_t)L1T * CDIM];   // Q proj fp16 (rms+rope applied in place)
__device__ __half g_bufh[(size_t)L1T * CDIM];   // fp16 qh, later fp16 attention out
__device__ __half g_kvw [NKV * CDIM];           // gathered fp16 kv window
__device__ float  g_k   [NKV * CDIM];
__device__ float  g_v   [NKV * CDIM];
__device__ float  g_heat[L1T];
__device__ __half g_w   [(size_t)4 * CDIM * CDIM];  // fp16 Wq, Wk, Wv, Wo

// ---------------- small helpers ----------------
__device__ __forceinline__ float blockReduceSum256(float v, float* s8) {
    int lane = threadIdx.x & 31, warp = threadIdx.x >> 5;
#pragma unroll
    for (int o = 16; o; o >>= 1) v += __shfl_xor_sync(0xffffffffu, v, o);
    if (lane == 0) s8[warp] = v;
    __syncthreads();
    float t = 0.f;
#pragma unroll
    for (int i = 0; i < 8; i++) t += s8[i];
    __syncthreads();
    return t;
}

__device__ __forceinline__ uint32_t smem_u32(const void* p) {
    uint32_t a;
    asm("{ .reg .u64 t; cvta.to.shared.u64 t, %1; cvt.u32.u64 %0, t; }" : "=r"(a) : "l"(p));
    return a;
}
__device__ __forceinline__ void cpa16(uint32_t s, const void* g) {
    asm volatile("cp.async.cg.shared.global [%0], [%1], 16;" :: "r"(s), "l"(g));
}
__device__ __forceinline__ void cpa_commit() {
    asm volatile("cp.async.commit_group;" ::: "memory");
}
__device__ __forceinline__ void ldsm4(uint32_t* r, uint32_t a) {
    asm volatile("ldmatrix.sync.aligned.m8n8.x4.shared.b16 {%0,%1,%2,%3}, [%4];"
                 : "=r"(r[0]), "=r"(r[1]), "=r"(r[2]), "=r"(r[3]) : "r"(a));
}
__device__ __forceinline__ void mma_f16(float* c, const uint32_t* a, uint32_t b0, uint32_t b1) {
    asm volatile(
        "mma.sync.aligned.m16n8k16.row.col.f32.f16.f16.f32 "
        "{%0,%1,%2,%3}, {%4,%5,%6,%7}, {%8,%9}, {%0,%1,%2,%3};\n"
        : "+f"(c[0]), "+f"(c[1]), "+f"(c[2]), "+f"(c[3])
        : "r"(a[0]), "r"(a[1]), "r"(a[2]), "r"(a[3]), "r"(b0), "r"(b1));
}

#define SWZ(x) ((x) ^ (((x) >> 3) & 0x70))

// ---------------- heat (block-per-row) + fp16 qh ----------------
__global__ void heat_kernel(const float* __restrict__ x, const float* __restrict__ te,
                            const float* __restrict__ mod, const float* __restrict__ Wh,
                            const float* __restrict__ bh) {
    __shared__ float s8[8];
    int row = blockIdx.x;
    const float* xr = x  + (size_t)row * CDIM;
    const float* tr = te + (size_t)row * CDIM;
    __half* rq = g_bufh + (size_t)row * CDIM;
    float xv[6], tv[6];
    float sum = 0.f, sq = 0.f;
#pragma unroll
    for (int i = 0; i < 6; i++) {
        int c = threadIdx.x + i * 256;
        xv[i] = xr[c]; tv[i] = tr[c];
        rq[c] = __float2half_rn(xv[i]);   // fp16 qh for the Q GEMM
        sum += xv[i]; sq += xv[i] * xv[i];
    }
    sum = blockReduceSum256(sum, s8);
    sq  = blockReduceSum256(sq,  s8);
    float mu  = sum * (1.f / CDIM);
    float var = sq * (1.f / CDIM) - mu * mu;
    float rs  = rsqrtf(var + 1e-6f);
    float dot = 0.f;
#pragma unroll
    for (int i = 0; i < 6; i++) {
        int c = threadIdx.x + i * 256;
        float ln = (xv[i] - mu) * rs;
        float y  = ln * (1.f + mod[CDIM + c] + tv[i]) + mod[c] + tv[i];
        dot += y * Wh[c];
    }
    dot = blockReduceSum256(dot, s8);
    if (threadIdx.x == 0)
        g_heat[row] = 1.f / (1.f + __expf(-(dot + bh[0])));
}

// ---------------- weights -> fp16 ----------------
__global__ void round_w(const float* __restrict__ Wq, const float* __restrict__ Wk,
                        const float* __restrict__ Wv, const float* __restrict__ Wo) {
    size_t t = (size_t)blockIdx.x * 256 + threadIdx.x;
    const size_t n4 = (size_t)CDIM * CDIM / 4;
    if (t >= n4) return;
    const float4* src[4] = {(const float4*)Wq, (const float4*)Wk,
                            (const float4*)Wv, (const float4*)Wo};
    __half2* dst = (__half2*)g_w;
#pragma unroll
    for (int m = 0; m < 4; m++) {
        float4 a = src[m][t];
        dst[m * n4 * 2 + t * 2 + 0] = __floats2half2_rn(a.x, a.y);
        dst[m * n4 * 2 + t * 2 + 1] = __floats2half2_rn(a.z, a.w);
    }
}

// ---------------- kv window gather (fp16) ----------------
__device__ __forceinline__ int audio_index(int b, int j) {
    int v = (b == 0) ? (-11 + j) : (8 * b - 10 + j);
    v = v < 0 ? 0 : v;
    return v > (L2A - 1) ? (L2A - 1) : v;
}

__global__ void gather_kvw(const float* __restrict__ kv) {
    int t = blockIdx.x * blockDim.x + threadIdx.x;
    const int C4 = CDIM / 4;
    if (t >= NKV * C4) return;
    int r = t / C4, c4 = t % C4;
    int b = r / SKV, s = r % SKV;
    int src = audio_index(b, s);
    float4 v = ((const float4*)kv)[(size_t)src * C4 + c4];
    __half2* dst = (__half2*)g_kvw;
    dst[((size_t)r * C4 + c4) * 2 + 0] = __floats2half2_rn(v.x, v.y);
    dst[((size_t)r * C4 + c4) * 2 + 1] = __floats2half2_rn(v.z, v.w);
}

// =====================================================================
// FP16 mma.sync GEMM, C[m][n] = sum_k A[m][k]*B[n][k] + bias[n]
// CTA tile 128(M) x 256(N), BK=64, 3-stage cp.async.
// 256 threads, 2(M) x 4(N) warp grid, 64x64 warp tiles, ldmatrix.x4.
// Rotated mainloop: barrier + next-tile step0 frag load happen inside
// ks==3, before its MMAs, so the tensor pipe stays fed across tiles.
// Ch != null -> fp16 output.
// =====================================================================
#define GBM 128
#define GBN 256
#define GBK 64
#define GTHR 256
#define A_STG 16384                       // 128 rows * 128 B
#define B_STG 32768                       // 256 rows * 128 B
#define STG_BYTES (A_STG + B_STG)         // 49152
#define NSTAGE 3
#define GSMEM_TOTAL (STG_BYTES * NSTAGE)  // 147456 B
#define NKT (CDIM / GBK)                  // 24
#define ESTRIDE 68                        // epilogue smem row stride (floats)

__global__ __launch_bounds__(GTHR, 1)
void gemm_tc(const __half* __restrict__ A, const __half* __restrict__ B,
             const float* __restrict__ bias, float* __restrict__ C,
             __half* __restrict__ Ch, int M)
{
    extern __shared__ float smem[];
    uint32_t sb = smem_u32(smem);
    const int tid = threadIdx.x;
    const int wid = tid >> 5, lane = tid & 31;
    const int wm = wid & 1, wn = wid >> 1;     // 2(M) x 4(N) warp grid
    const int bm = blockIdx.x, bn = blockIdx.y;

    const int a_row = (lane & 7) + ((lane >> 3) & 1) * 8;
    const int a_kh  = (lane >> 4) * 16;
    const int b_row = (lane & 7) + (lane >> 4) * 8;
    const int b_kh  = ((lane >> 3) & 1) * 16;

    float acc[4][8][4];
#pragma unroll
    for (int mt = 0; mt < 4; mt++)
#pragma unroll
        for (int nt = 0; nt < 8; nt++)
#pragma unroll
            for (int i = 0; i < 4; i++) acc[mt][nt][i] = 0.f;

#define LOAD_STAGE(sidx, ktile) do {                                             \
        uint32_t base_ = sb + (uint32_t)(sidx) * STG_BYTES;                      \
        int kc_ = (ktile) * GBK;                                                 \
        _Pragma("unroll")                                                        \
        for (int i_ = 0; i_ < 4; i_++) {                                         \
            int idx_ = i_ * GTHR + tid;                                          \
            int row_ = idx_ >> 3, c_ = idx_ & 7;                                 \
            int gr_ = bm * GBM + row_; gr_ = gr_ < M ? gr_ : M - 1;              \
            cpa16(base_ + SWZ(row_ * 128 + c_ * 16),                             \
                  A + (size_t)gr_ * CDIM + kc_ + c_ * 8);                        \
        }                                                                        \
        _Pragma("unroll")                                                        \
        for (int i_ = 0; i_ < 8; i_++) {                                         \
            int idx_ = i_ * GTHR + tid;                                          \
            int row_ = idx_ >> 3, c_ = idx_ & 7;                                 \
            cpa16(base_ + A_STG + SWZ(row_ * 128 + c_ * 16),                     \
                  B + (size_t)(bn * GBN + row_) * CDIM + kc_ + c_ * 8);          \
        }                                                                        \
        cpa_commit();                                                            \
    } while (0)

// load all 8 fragments of one k16-step into buffer slot s_
#define LDFRAGS(s_, As_, Bs_, kb_) do {                                          \
        _Pragma("unroll")                                                        \
        for (int mt_ = 0; mt_ < 4; mt_++)                                        \
            ldsm4(af[s_][mt_], (As_) + SWZ((wm * 64 + mt_ * 16 + a_row) * 128 + (kb_) + a_kh)); \
        _Pragma("unroll")                                                        \
        for (int nt_ = 0; nt_ < 4; nt_++)                                        \
            ldsm4(bf[s_][nt_], (Bs_) + SWZ((wn * 64 + nt_ * 16 + b_row) * 128 + (kb_) + b_kh)); \
    } while (0)

#define MMASTEP(s_) do {                                                         \
        _Pragma("unroll")                                                        \
        for (int nt_ = 0; nt_ < 4; nt_++)                                        \
            _Pragma("unroll")                                                    \
            for (int mt_ = 0; mt_ < 4; mt_++) {                                  \
                mma_f16(acc[mt_][2 * nt_],     af[s_][mt_], bf[s_][nt_][0], bf[s_][nt_][1]); \
                mma_f16(acc[mt_][2 * nt_ + 1], af[s_][mt_], bf[s_][nt_][2], bf[s_][nt_][3]); \
            }                                                                    \
    } while (0)

    uint32_t af[2][4][4], bf[2][4][4];

    // prologue: stages 0 and 1 in flight; wait stage 0, preload its step0 frags
    LOAD_STAGE(0, 0);
    LOAD_STAGE(1, 1);
    asm volatile("cp.async.wait_group 1;" ::: "memory");
    __syncthreads();
    {
        uint32_t As0 = sb, Bs0 = sb + A_STG;
        LDFRAGS(0, As0, Bs0, 0);
    }

#pragma unroll 1
    for (int kt = 0; kt < NKT; kt++) {
        uint32_t As = sb + (uint32_t)(kt % NSTAGE) * STG_BYTES;
        uint32_t Bs = As + A_STG;
        // steps 0..2: prefetch next step's frags from current stage, then MMA
        LDFRAGS(1, As, Bs, 32);
        if (kt + 2 < NKT) LOAD_STAGE((kt + 2) % NSTAGE, kt + 2);
        MMASTEP(0);
        LDFRAGS(0, As, Bs, 64);
        MMASTEP(1);
        LDFRAGS(1, As, Bs, 96);
        MMASTEP(0);
        // step 3: make next stage visible, preload its step0 frags, then MMA
        if (kt + 1 < NKT) {
            // NOTE: when no LOAD_STAGE was issued this tile (kt+2 >= NKT), the
            // newest outstanding group IS the stage we need -> must wait_group 0.
            if (kt + 2 < NKT) asm volatile("cp.async.wait_group 1;" ::: "memory");
            else              asm volatile("cp.async.wait_group 0;" ::: "memory");
            __syncthreads();
            uint32_t As2 = sb + (uint32_t)((kt + 1) % NSTAGE) * STG_BYTES;
            LDFRAGS(0, As2, As2 + A_STG, 0);
        }
        MMASTEP(1);
    }
    __syncthreads();

    // ---- epilogue: stage 128x64 column-chunks through smem, coalesced stores ----
    const int gid = lane >> 2, tig = lane & 3;
    float* es = smem;   // [128][ESTRIDE]
#pragma unroll 1
    for (int c = 0; c < 4; c++) {
        if (wn == c) {
#pragma unroll
            for (int mt = 0; mt < 4; mt++) {
#pragma unroll
                for (int nt = 0; nt < 8; nt++) {
                    int row = wm * 64 + mt * 16 + gid;
                    int col = nt * 8 + tig * 2;
                    *(float2*)&es[row * ESTRIDE + col] =
                        make_float2(acc[mt][nt][0], acc[mt][nt][1]);
                    *(float2*)&es[(row + 8) * ESTRIDE + col] =
                        make_float2(acc[mt][nt][2], acc[mt][nt][3]);
                }
            }
        }
        __syncthreads();
#pragma unroll
        for (int it = 0; it < 8; it++) {
            int idx = it * GTHR + tid;
            int row = idx >> 4, c4 = idx & 15;
            int gr = bm * GBM + row;
            if (gr < M) {
                int gc = bn * GBN + c * 64 + c4 * 4;
                const float* ep = &es[row * ESTRIDE + c4 * 4];
                float4 o;
                o.x = ep[0] + bias[gc + 0];
                o.y = ep[1] + bias[gc + 1];
                o.z = ep[2] + bias[gc + 2];
                o.w = ep[3] + bias[gc + 3];
                if (Ch) {
                    __half2* dp = (__half2*)(Ch + (size_t)gr * CDIM + gc);
                    dp[0] = __floats2half2_rn(o.x, o.y);
                    dp[1] = __floats2half2_rn(o.z, o.w);
                } else {
                    *(float4*)(C + (size_t)gr * CDIM + gc) = o;
                }
            }
        }
        __syncthreads();
    }
#undef LOAD_STAGE
#undef LDFRAGS
#undef MMASTEP
}

// ---------------- Q rms + rope (in-place on fp16 g_qh) ----------------
__global__ void q_rmsrope_kernel(const float* __restrict__ gqw, const float* __restrict__ qf) {
    __shared__ float s8[8];
    int row = blockIdx.x;
    __half2* base = (__half2*)(g_qh + (size_t)row * CDIM);
    float2 v[3];
    float sq = 0.f;
#pragma unroll
    for (int i = 0; i < 3; i++) {
        int p = threadIdx.x + i * 256;
        v[i] = __half22float2(base[p]);
        sq += v[i].x * v[i].x + v[i].y * v[i].y;
    }
    sq = blockReduceSum256(sq, s8);
    float rs = rsqrtf(sq * (1.f / CDIM) + 1e-6f);
    int h = row % HWD / WW, w = row % WW;
#pragma unroll
    for (int i = 0; i < 3; i++) {
        int p = threadIdx.x + i * 256;
        int j = p & 63;
        int pos = (j < 22) ? 0 : ((j < 43) ? h : w);
        float cs = qf[pos * 128 + 2 * j];
        float sn = qf[pos * 128 + 2 * j + 1];
        float ar = v[i].x * rs * gqw[2 * p];
        float ai = v[i].y * rs * gqw[2 * p + 1];
        base[p] = __floats2half2_rn(ar * cs - ai * sn, ar * sn + ai * cs);
    }
}

// ---------------- K rms + rope (in-place on g_k) ----------------
__global__ void k_rmsrope_kernel(const float* __restrict__ gkw, const float* __restrict__ kf) {
    __shared__ float s8[8];
    int row = blockIdx.x;
    float* base = g_k + (size_t)row * CDIM;
    float xr[3], xi[3];
    float sq = 0.f;
#pragma unroll
    for (int i = 0; i < 3; i++) {
        int p = threadIdx.x + i * 256;
        float2 v = ((float2*)base)[p];
        xr[i] = v.x; xi[i] = v.y;
        sq += v.x * v.x + v.y * v.y;
    }
    sq = blockReduceSum256(sq, s8);
    float rs = rsqrtf(sq * (1.f / CDIM) + 1e-6f);
    int s = row % SKV;
#pragma unroll
    for (int i = 0; i < 3; i++) {
        int p = threadIdx.x + i * 256;
        int j = p & 63;
        int pos = (j < 22) ? s : 0;
        float cs = kf[pos * 128 + 2 * j];
        float sn = kf[pos * 128 + 2 * j + 1];
        float ar = xr[i] * rs * gkw[2 * p];
        float ai = xi[i] * rs * gkw[2 * p + 1];
        ((float2*)base)[p] = make_float2(ar * cs - ai * sn, ar * sn + ai * cs);
    }
}

// ---------------- attention: softmax(QK^T/sqrt(128)) V * heat -> fp16 ----------------
__global__ __launch_bounds__(256) void attn_kernel() {
    __shared__ float ks[SKV][HD];
    __shared__ float vs[SKV][HD];
    int b = blockIdx.z, head = blockIdx.y, row0 = blockIdx.x * 64;
    for (int t = threadIdx.x; t < SKV * HD; t += 256) {
        int s = t >> 7, d = t & 127;
        size_t off = (size_t)(b * SKV + s) * CDIM + head * HD + d;
        ks[s][d] = g_k[off];
        vs[s][d] = g_v[off];
    }
    __syncthreads();
    int warp = threadIdx.x >> 5, lane = threadIdx.x & 31;
#pragma unroll 1
    for (int r = 0; r < 8; r++) {
        int row = row0 + warp * 8 + r;
        if (row >= HWD) break;
        int grow = b * HWD + row;
        const __half2* qh2 = (const __half2*)(g_qh + (size_t)grow * CDIM + head * HD + lane * 4);
        float2 f0 = __half22float2(qh2[0]), f1 = __half22float2(qh2[1]);
        float4 q4 = make_float4(f0.x, f0.y, f1.x, f1.y);
        float sc[16];
#pragma unroll
        for (int s = 0; s < 16; s++) {
            float4 k4 = *(float4*)&ks[s][lane * 4];
            sc[s] = q4.x * k4.x + q4.y * k4.y + q4.z * k4.z + q4.w * k4.w;
        }
#pragma unroll
        for (int o = 16; o; o >>= 1)
#pragma unroll
            for (int s = 0; s < 16; s++)
                sc[s] += __shfl_xor_sync(0xffffffffu, sc[s], o);
        float m = -1e30f;
#pragma unroll
        for (int s = 0; s < 16; s++) {
            sc[s] *= 0.08838834764831843f;  // 1/sqrt(128)
            m = fmaxf(m, sc[s]);
        }
        float sum = 0.f;
#pragma unroll
        for (int s = 0; s < 16; s++) { sc[s] = __expf(sc[s] - m); sum += sc[s]; }
        float scale = g_heat[grow] / sum;
        float ox = 0.f, oy = 0.f, oz = 0.f, ow = 0.f;
#pragma unroll
        for (int s = 0; s < 16; s++) {
            float4 v4 = *(float4*)&vs[s][lane * 4];
            ox += sc[s] * v4.x; oy += sc[s] * v4.y;
            oz += sc[s] * v4.z; ow += sc[s] * v4.w;
        }
        __half2* dst = (__half2*)(g_bufh + (size_t)grow * CDIM + head * HD + lane * 4);
        dst[0] = __floats2half2_rn(ox * scale, oy * scale);
        dst[1] = __floats2half2_rn(oz * scale, ow * scale);
    }
}

// ---------------- launch ----------------
extern "C" void kernel_launch(void* const* d_in, const int* in_sizes, int n_in,
                              void* d_out, int out_size) {
    const float* qh  = (const float*)d_in[0];
    const float* kvh = (const float*)d_in[1];
    const float* te  = (const float*)d_in[2];
    const float* qf  = (const float*)d_in[4];
    const float* kvf = (const float*)d_in[5];
    const float* Wq  = (const float*)d_in[6];
    const float* bq  = (const float*)d_in[7];
    const float* Wk  = (const float*)d_in[8];
    const float* bk  = (const float*)d_in[9];
    const float* Wv  = (const float*)d_in[10];
    const float* bv  = (const float*)d_in[11];
    const float* Wo  = (const float*)d_in[12];
    const float* bo  = (const float*)d_in[13];
    const float* gqw = (const float*)d_in[14];
    const float* gkw = (const float*)d_in[15];
    const float* mod = (const float*)d_in[16];
    const float* Wh  = (const float*)d_in[17];
    const float* bh  = (const float*)d_in[18];
    float* out = (float*)d_out;

    float *kbuf, *vbuf;
    __half *qhbuf, *bufh, *kvw, *gw;
    cudaGetSymbolAddress((void**)&qhbuf, g_qh);
    cudaGetSymbolAddress((void**)&bufh,  g_bufh);
    cudaGetSymbolAddress((void**)&kvw,   g_kvw);
    cudaGetSymbolAddress((void**)&kbuf,  g_k);
    cudaGetSymbolAddress((void**)&vbuf,  g_v);
    cudaGetSymbolAddress((void**)&gw,    g_w);
    const size_t NW = (size_t)CDIM * CDIM;

    static bool attr_set = false;
    if (!attr_set) {
        cudaFuncSetAttribute(gemm_tc, cudaFuncAttributeMaxDynamicSharedMemorySize, GSMEM_TOTAL);
        attr_set = true;
    }

    heat_kernel<<<L1T, 256>>>(qh, te, mod, Wh, bh);          // g_heat + fp16 qh -> bufh
    round_w<<<(int)((NW / 4 + 255) / 256), 256>>>(Wq, Wk, Wv, Wo);
    gather_kvw<<<(NKV * (CDIM / 4) + 255) / 256, 256>>>(kvh);

    gemm_tc<<<dim3((L1T + GBM - 1) / GBM, CDIM / GBN), GTHR, GSMEM_TOTAL>>>(
        bufh, gw, bq, nullptr, qhbuf, L1T);                  // Q proj -> fp16 g_qh
    gemm_tc<<<dim3((NKV + GBM - 1) / GBM, CDIM / GBN), GTHR, GSMEM_TOTAL>>>(
        kvw, gw + NW, bk, kbuf, nullptr, NKV);
    gemm_tc<<<dim3((NKV + GBM - 1) / GBM, CDIM / GBN), GTHR, GSMEM_TOTAL>>>(
        kvw, gw + 2 * NW, bv, vbuf, nullptr, NKV);

    q_rmsrope_kernel<<<L1T, 256>>>(gqw, qf);                 // in-place fp16
    k_rmsrope_kernel<<<NKV, 256>>>(gkw, kvf);

    attn_kernel<<<dim3((HWD + 63) / 64, NH, T_FR), 256>>>(); // fp16 attn-out -> bufh

    gemm_tc<<<dim3((L1T + GBM - 1) / GBM, CDIM / GBN), GTHR, GSMEM_TOTAL>>>(
        bufh, gw + 3 * NW, bo, out, nullptr, L1T);
}

// round 14
// speedup vs baseline: 1.1294x; 1.0632x over previous
#include <cuda_runtime.h>
#include <cuda_fp16.h>
#include <cstdint>

#define T_FR 21
#define HH   30
#define WW   52
#define HWD  1560
#define L1T  32760
#define L2A  162
#define NH   12
#define HD   128
#define CDIM 1536
#define SKV  16
#define NKV  336   // 21*16

// ---------------- scratch (no allocations allowed) ----------------
__device__ __half g_qh  [(size_t)L1T * CDIM];   // Q proj fp16 (rms+rope applied in place)
__device__ __half g_bufh[(size_t)L1T * CDIM];   // fp16 qh, later fp16 attention out
__device__ __half g_kvw [NKV * CDIM];           // gathered fp16 kv window
__device__ float  g_k   [NKV * CDIM];
__device__ float  g_v   [NKV * CDIM];
__device__ float  g_heat[L1T];
__device__ __half g_w   [(size_t)4 * CDIM * CDIM];  // fp16 Wq, Wk, Wv, Wo

// ---------------- small helpers ----------------
__device__ __forceinline__ float blockReduceSum256(float v, float* s8) {
    int lane = threadIdx.x & 31, warp = threadIdx.x >> 5;
#pragma unroll
    for (int o = 16; o; o >>= 1) v += __shfl_xor_sync(0xffffffffu, v, o);
    if (lane == 0) s8[warp] = v;
    __syncthreads();
    float t = 0.f;
#pragma unroll
    for (int i = 0; i < 8; i++) t += s8[i];
    __syncthreads();
    return t;
}

__device__ __forceinline__ uint32_t smem_u32(const void* p) {
    uint32_t a;
    asm("{ .reg .u64 t; cvta.to.shared.u64 t, %1; cvt.u32.u64 %0, t; }" : "=r"(a) : "l"(p));
    return a;
}
__device__ __forceinline__ void cpa16(uint32_t s, const void* g) {
    asm volatile("cp.async.cg.shared.global [%0], [%1], 16;" :: "r"(s), "l"(g));
}
__device__ __forceinline__ void cpa_commit() {
    asm volatile("cp.async.commit_group;" ::: "memory");
}
__device__ __forceinline__ void ldsm4(uint32_t* r, uint32_t a) {
    asm volatile("ldmatrix.sync.aligned.m8n8.x4.shared.b16 {%0,%1,%2,%3}, [%4];"
                 : "=r"(r[0]), "=r"(r[1]), "=r"(r[2]), "=r"(r[3]) : "r"(a));
}
__device__ __forceinline__ void mma_f16(float* c, const uint32_t* a, uint32_t b0, uint32_t b1) {
    asm volatile(
        "mma.sync.aligned.m16n8k16.row.col.f32.f16.f16.f32 "
        "{%0,%1,%2,%3}, {%4,%5,%6,%7}, {%8,%9}, {%0,%1,%2,%3};\n"
        : "+f"(c[0]), "+f"(c[1]), "+f"(c[2]), "+f"(c[3])
        : "r"(a[0]), "r"(a[1]), "r"(a[2]), "r"(a[3]), "r"(b0), "r"(b1));
}

#define SWZ(x) ((x) ^ (((x) >> 3) & 0x70))

// ---------------- heat (block-per-row) + fp16 qh ----------------
__global__ void heat_kernel(const float* __restrict__ x, const float* __restrict__ te,
                            const float* __restrict__ mod, const float* __restrict__ Wh,
                            const float* __restrict__ bh) {
    __shared__ float s8[8];
    int row = blockIdx.x;
    const float* xr = x  + (size_t)row * CDIM;
    const float* tr = te + (size_t)row * CDIM;
    __half* rq = g_bufh + (size_t)row * CDIM;
    float xv[6], tv[6];
    float sum = 0.f, sq = 0.f;
#pragma unroll
    for (int i = 0; i < 6; i++) {
        int c = threadIdx.x + i * 256;
        xv[i] = xr[c]; tv[i] = tr[c];
        rq[c] = __float2half_rn(xv[i]);   // fp16 qh for the Q GEMM
        sum += xv[i]; sq += xv[i] * xv[i];
    }
    sum = blockReduceSum256(sum, s8);
    sq  = blockReduceSum256(sq,  s8);
    float mu  = sum * (1.f / CDIM);
    float var = sq * (1.f / CDIM) - mu * mu;
    float rs  = rsqrtf(var + 1e-6f);
    float dot = 0.f;
#pragma unroll
    for (int i = 0; i < 6; i++) {
        int c = threadIdx.x + i * 256;
        float ln = (xv[i] - mu) * rs;
        float y  = ln * (1.f + mod[CDIM + c] + tv[i]) + mod[c] + tv[i];
        dot += y * Wh[c];
    }
    dot = blockReduceSum256(dot, s8);
    if (threadIdx.x == 0)
        g_heat[row] = 1.f / (1.f + __expf(-(dot + bh[0])));
}

// ---------------- weights -> fp16 ----------------
__global__ void round_w(const float* __restrict__ Wq, const float* __restrict__ Wk,
                        const float* __restrict__ Wv, const float* __restrict__ Wo) {
    size_t t = (size_t)blockIdx.x * 256 + threadIdx.x;
    const size_t n4 = (size_t)CDIM * CDIM / 4;
    if (t >= n4) return;
    const float4* src[4] = {(const float4*)Wq, (const float4*)Wk,
                            (const float4*)Wv, (const float4*)Wo};
    __half2* dst = (__half2*)g_w;
#pragma unroll
    for (int m = 0; m < 4; m++) {
        float4 a = src[m][t];
        dst[m * n4 * 2 + t * 2 + 0] = __floats2half2_rn(a.x, a.y);
        dst[m * n4 * 2 + t * 2 + 1] = __floats2half2_rn(a.z, a.w);
    }
}

// ---------------- kv window gather (fp16) ----------------
__device__ __forceinline__ int audio_index(int b, int j) {
    int v = (b == 0) ? (-11 + j) : (8 * b - 10 + j);
    v = v < 0 ? 0 : v;
    return v > (L2A - 1) ? (L2A - 1) : v;
}

__global__ void gather_kvw(const float* __restrict__ kv) {
    int t = blockIdx.x * blockDim.x + threadIdx.x;
    const int C4 = CDIM / 4;
    if (t >= NKV * C4) return;
    int r = t / C4, c4 = t % C4;
    int b = r / SKV, s = r % SKV;
    int src = audio_index(b, s);
    float4 v = ((const float4*)kv)[(size_t)src * C4 + c4];
    __half2* dst = (__half2*)g_kvw;
    dst[((size_t)r * C4 + c4) * 2 + 0] = __floats2half2_rn(v.x, v.y);
    dst[((size_t)r * C4 + c4) * 2 + 1] = __floats2half2_rn(v.z, v.w);
}

// =====================================================================
// FP16 mma.sync GEMM (R13 rotated-mainloop version, unchanged)
// =====================================================================
#define GBM 128
#define GBN 256
#define GBK 64
#define GTHR 256
#define A_STG 16384
#define B_STG 32768
#define STG_BYTES (A_STG + B_STG)
#define NSTAGE 3
#define GSMEM_TOTAL (STG_BYTES * NSTAGE)
#define NKT (CDIM / GBK)
#define ESTRIDE 68

__global__ __launch_bounds__(GTHR, 1)
void gemm_tc(const __half* __restrict__ A, const __half* __restrict__ B,
             const float* __restrict__ bias, float* __restrict__ C,
             __half* __restrict__ Ch, int M)
{
    extern __shared__ float smem[];
    uint32_t sb = smem_u32(smem);
    const int tid = threadIdx.x;
    const int wid = tid >> 5, lane = tid & 31;
    const int wm = wid & 1, wn = wid >> 1;
    const int bm = blockIdx.x, bn = blockIdx.y;

    const int a_row = (lane & 7) + ((lane >> 3) & 1) * 8;
    const int a_kh  = (lane >> 4) * 16;
    const int b_row = (lane & 7) + (lane >> 4) * 8;
    const int b_kh  = ((lane >> 3) & 1) * 16;

    float acc[4][8][4];
#pragma unroll
    for (int mt = 0; mt < 4; mt++)
#pragma unroll
        for (int nt = 0; nt < 8; nt++)
#pragma unroll
            for (int i = 0; i < 4; i++) acc[mt][nt][i] = 0.f;

#define LOAD_STAGE(sidx, ktile) do {                                             \
        uint32_t base_ = sb + (uint32_t)(sidx) * STG_BYTES;                      \
        int kc_ = (ktile) * GBK;                                                 \
        _Pragma("unroll")                                                        \
        for (int i_ = 0; i_ < 4; i_++) {                                         \
            int idx_ = i_ * GTHR + tid;                                          \
            int row_ = idx_ >> 3, c_ = idx_ & 7;                                 \
            int gr_ = bm * GBM + row_; gr_ = gr_ < M ? gr_ : M - 1;              \
            cpa16(base_ + SWZ(row_ * 128 + c_ * 16),                             \
                  A + (size_t)gr_ * CDIM + kc_ + c_ * 8);                        \
        }                                                                        \
        _Pragma("unroll")                                                        \
        for (int i_ = 0; i_ < 8; i_++) {                                         \
            int idx_ = i_ * GTHR + tid;                                          \
            int row_ = idx_ >> 3, c_ = idx_ & 7;                                 \
            cpa16(base_ + A_STG + SWZ(row_ * 128 + c_ * 16),                     \
                  B + (size_t)(bn * GBN + row_) * CDIM + kc_ + c_ * 8);          \
        }                                                                        \
        cpa_commit();                                                            \
    } while (0)

#define LDFRAGS(s_, As_, Bs_, kb_) do {                                          \
        _Pragma("unroll")                                                        \
        for (int mt_ = 0; mt_ < 4; mt_++)                                        \
            ldsm4(af[s_][mt_], (As_) + SWZ((wm * 64 + mt_ * 16 + a_row) * 128 + (kb_) + a_kh)); \
        _Pragma("unroll")                                                        \
        for (int nt_ = 0; nt_ < 4; nt_++)                                        \
            ldsm4(bf[s_][nt_], (Bs_) + SWZ((wn * 64 + nt_ * 16 + b_row) * 128 + (kb_) + b_kh)); \
    } while (0)

#define MMASTEP(s_) do {                                                         \
        _Pragma("unroll")                                                        \
        for (int nt_ = 0; nt_ < 4; nt_++)                                        \
            _Pragma("unroll")                                                    \
            for (int mt_ = 0; mt_ < 4; mt_++) {                                  \
                mma_f16(acc[mt_][2 * nt_],     af[s_][mt_], bf[s_][nt_][0], bf[s_][nt_][1]); \
                mma_f16(acc[mt_][2 * nt_ + 1], af[s_][mt_], bf[s_][nt_][2], bf[s_][nt_][3]); \
            }                                                                    \
    } while (0)

    uint32_t af[2][4][4], bf[2][4][4];

    LOAD_STAGE(0, 0);
    LOAD_STAGE(1, 1);
    asm volatile("cp.async.wait_group 1;" ::: "memory");
    __syncthreads();
    {
        uint32_t As0 = sb, Bs0 = sb + A_STG;
        LDFRAGS(0, As0, Bs0, 0);
    }

#pragma unroll 1
    for (int kt = 0; kt < NKT; kt++) {
        uint32_t As = sb + (uint32_t)(kt % NSTAGE) * STG_BYTES;
        uint32_t Bs = As + A_STG;
        LDFRAGS(1, As, Bs, 32);
        if (kt + 2 < NKT) LOAD_STAGE((kt + 2) % NSTAGE, kt + 2);
        MMASTEP(0);
        LDFRAGS(0, As, Bs, 64);
        MMASTEP(1);
        LDFRAGS(1, As, Bs, 96);
        MMASTEP(0);
        if (kt + 1 < NKT) {
            if (kt + 2 < NKT) asm volatile("cp.async.wait_group 1;" ::: "memory");
            else              asm volatile("cp.async.wait_group 0;" ::: "memory");
            __syncthreads();
            uint32_t As2 = sb + (uint32_t)((kt + 1) % NSTAGE) * STG_BYTES;
            LDFRAGS(0, As2, As2 + A_STG, 0);
        }
        MMASTEP(1);
    }
    __syncthreads();

    const int gid = lane >> 2, tig = lane & 3;
    float* es = smem;
#pragma unroll 1
    for (int c = 0; c < 4; c++) {
        if (wn == c) {
#pragma unroll
            for (int mt = 0; mt < 4; mt++) {
#pragma unroll
                for (int nt = 0; nt < 8; nt++) {
                    int row = wm * 64 + mt * 16 + gid;
                    int col = nt * 8 + tig * 2;
                    *(float2*)&es[row * ESTRIDE + col] =
                        make_float2(acc[mt][nt][0], acc[mt][nt][1]);
                    *(float2*)&es[(row + 8) * ESTRIDE + col] =
                        make_float2(acc[mt][nt][2], acc[mt][nt][3]);
                }
            }
        }
        __syncthreads();
#pragma unroll
        for (int it = 0; it < 8; it++) {
            int idx = it * GTHR + tid;
            int row = idx >> 4, c4 = idx & 15;
            int gr = bm * GBM + row;
            if (gr < M) {
                int gc = bn * GBN + c * 64 + c4 * 4;
                const float* ep = &es[row * ESTRIDE + c4 * 4];
                float4 o;
                o.x = ep[0] + bias[gc + 0];
                o.y = ep[1] + bias[gc + 1];
                o.z = ep[2] + bias[gc + 2];
                o.w = ep[3] + bias[gc + 3];
                if (Ch) {
                    __half2* dp = (__half2*)(Ch + (size_t)gr * CDIM + gc);
                    dp[0] = __floats2half2_rn(o.x, o.y);
                    dp[1] = __floats2half2_rn(o.z, o.w);
                } else {
                    *(float4*)(C + (size_t)gr * CDIM + gc) = o;
                }
            }
        }
        __syncthreads();
    }
#undef LOAD_STAGE
#undef LDFRAGS
#undef MMASTEP
}

// ---------------- Q rms + rope (in-place on fp16 g_qh) ----------------
__global__ void q_rmsrope_kernel(const float* __restrict__ gqw, const float* __restrict__ qf) {
    __shared__ float s8[8];
    int row = blockIdx.x;
    __half2* base = (__half2*)(g_qh + (size_t)row * CDIM);
    float2 v[3];
    float sq = 0.f;
#pragma unroll
    for (int i = 0; i < 3; i++) {
        int p = threadIdx.x + i * 256;
        v[i] = __half22float2(base[p]);
        sq += v[i].x * v[i].x + v[i].y * v[i].y;
    }
    sq = blockReduceSum256(sq, s8);
    float rs = rsqrtf(sq * (1.f / CDIM) + 1e-6f);
    int h = row % HWD / WW, w = row % WW;
#pragma unroll
    for (int i = 0; i < 3; i++) {
        int p = threadIdx.x + i * 256;
        int j = p & 63;
        int pos = (j < 22) ? 0 : ((j < 43) ? h : w);
        float cs = qf[pos * 128 + 2 * j];
        float sn = qf[pos * 128 + 2 * j + 1];
        float ar = v[i].x * rs * gqw[2 * p];
        float ai = v[i].y * rs * gqw[2 * p + 1];
        base[p] = __floats2half2_rn(ar * cs - ai * sn, ar * sn + ai * cs);
    }
}

// ---------------- K rms + rope (in-place on g_k) ----------------
__global__ void k_rmsrope_kernel(const float* __restrict__ gkw, const float* __restrict__ kf) {
    __shared__ float s8[8];
    int row = blockIdx.x;
    float* base = g_k + (size_t)row * CDIM;
    float xr[3], xi[3];
    float sq = 0.f;
#pragma unroll
    for (int i = 0; i < 3; i++) {
        int p = threadIdx.x + i * 256;
        float2 v = ((float2*)base)[p];
        xr[i] = v.x; xi[i] = v.y;
        sq += v.x * v.x + v.y * v.y;
    }
    sq = blockReduceSum256(sq, s8);
    float rs = rsqrtf(sq * (1.f / CDIM) + 1e-6f);
    int s = row % SKV;
#pragma unroll
    for (int i = 0; i < 3; i++) {
        int p = threadIdx.x + i * 256;
        int j = p & 63;
        int pos = (j < 22) ? s : 0;
        float cs = kf[pos * 128 + 2 * j];
        float sn = kf[pos * 128 + 2 * j + 1];
        float ar = xr[i] * rs * gkw[2 * p];
        float ai = xi[i] * rs * gkw[2 * p + 1];
        ((float2*)base)[p] = make_float2(ar * cs - ai * sn, ar * sn + ai * cs);
    }
}

// ---------------- attention: softmax(QK^T/sqrt(128)) V * heat -> fp16 ----------------
__global__ __launch_bounds__(256) void attn_kernel() {
    __shared__ float ks[SKV][HD];
    __shared__ float vs[SKV][HD];
    int b = blockIdx.z, head = blockIdx.y, row0 = blockIdx.x * 64;
    for (int t = threadIdx.x; t < SKV * HD; t += 256) {
        int s = t >> 7, d = t & 127;
        size_t off = (size_t)(b * SKV + s) * CDIM + head * HD + d;
        ks[s][d] = g_k[off];
        vs[s][d] = g_v[off];
    }
    __syncthreads();
    int warp = threadIdx.x >> 5, lane = threadIdx.x & 31;
#pragma unroll 1
    for (int r = 0; r < 8; r++) {
        int row = row0 + warp * 8 + r;
        if (row >= HWD) break;
        int grow = b * HWD + row;
        const __half2* qh2 = (const __half2*)(g_qh + (size_t)grow * CDIM + head * HD + lane * 4);
        float2 f0 = __half22float2(qh2[0]), f1 = __half22float2(qh2[1]);
        float4 q4 = make_float4(f0.x, f0.y, f1.x, f1.y);
        float sc[16];
#pragma unroll
        for (int s = 0; s < 16; s++) {
            float4 k4 = *(float4*)&ks[s][lane * 4];
            sc[s] = q4.x * k4.x + q4.y * k4.y + q4.z * k4.z + q4.w * k4.w;
        }
#pragma unroll
        for (int o = 16; o; o >>= 1)
#pragma unroll
            for (int s = 0; s < 16; s++)
                sc[s] += __shfl_xor_sync(0xffffffffu, sc[s], o);
        float m = -1e30f;
#pragma unroll
        for (int s = 0; s < 16; s++) {
            sc[s] *= 0.08838834764831843f;  // 1/sqrt(128)
            m = fmaxf(m, sc[s]);
        }
        float sum = 0.f;
#pragma unroll
        for (int s = 0; s < 16; s++) { sc[s] = __expf(sc[s] - m); sum += sc[s]; }
        float scale = g_heat[grow] / sum;
        float ox = 0.f, oy = 0.f, oz = 0.f, ow = 0.f;
#pragma unroll
        for (int s = 0; s < 16; s++) {
            float4 v4 = *(float4*)&vs[s][lane * 4];
            ox += sc[s] * v4.x; oy += sc[s] * v4.y;
            oz += sc[s] * v4.z; ow += sc[s] * v4.w;
        }
        __half2* dst = (__half2*)(g_bufh + (size_t)grow * CDIM + head * HD + lane * 4);
        dst[0] = __floats2half2_rn(ox * scale, oy * scale);
        dst[1] = __floats2half2_rn(oz * scale, ow * scale);
    }
}

// ---------------- launch (two graph branches: Q-chain || KV-chain) ----------------
extern "C" void kernel_launch(void* const* d_in, const int* in_sizes, int n_in,
                              void* d_out, int out_size) {
    const float* qh  = (const float*)d_in[0];
    const float* kvh = (const float*)d_in[1];
    const float* te  = (const float*)d_in[2];
    const float* qf  = (const float*)d_in[4];
    const float* kvf = (const float*)d_in[5];
    const float* Wq  = (const float*)d_in[6];
    const float* bq  = (const float*)d_in[7];
    const float* Wk  = (const float*)d_in[8];
    const float* bk  = (const float*)d_in[9];
    const float* Wv  = (const float*)d_in[10];
    const float* bv  = (const float*)d_in[11];
    const float* Wo  = (const float*)d_in[12];
    const float* bo  = (const float*)d_in[13];
    const float* gqw = (const float*)d_in[14];
    const float* gkw = (const float*)d_in[15];
    const float* mod = (const float*)d_in[16];
    const float* Wh  = (const float*)d_in[17];
    const float* bh  = (const float*)d_in[18];
    float* out = (float*)d_out;

    float *kbuf, *vbuf;
    __half *qhbuf, *bufh, *kvw, *gw;
    cudaGetSymbolAddress((void**)&qhbuf, g_qh);
    cudaGetSymbolAddress((void**)&bufh,  g_bufh);
    cudaGetSymbolAddress((void**)&kvw,   g_kvw);
    cudaGetSymbolAddress((void**)&kbuf,  g_k);
    cudaGetSymbolAddress((void**)&vbuf,  g_v);
    cudaGetSymbolAddress((void**)&gw,    g_w);
    const size_t NW = (size_t)CDIM * CDIM;

    static bool init_done = false;
    static cudaStream_t s2;
    static cudaEvent_t evFork, evJoin;
    if (!init_done) {
        cudaFuncSetAttribute(gemm_tc, cudaFuncAttributeMaxDynamicSharedMemorySize, GSMEM_TOTAL);
        cudaStreamCreateWithFlags(&s2, cudaStreamNonBlocking);
        cudaEventCreateWithFlags(&evFork, cudaEventDisableTiming);
        cudaEventCreateWithFlags(&evJoin, cudaEventDisableTiming);
        init_done = true;
    }

    // main stream: weights first (both branches need g_w)
    round_w<<<(int)((NW / 4 + 255) / 256), 256>>>(Wq, Wk, Wv, Wo);
    cudaEventRecord(evFork, 0);

    // ---- branch B (stream s2): gather -> K GEMM -> V GEMM -> K rms+rope ----
    cudaStreamWaitEvent(s2, evFork, 0);
    gather_kvw<<<(NKV * (CDIM / 4) + 255) / 256, 256, 0, s2>>>(kvh);
    gemm_tc<<<dim3((NKV + GBM - 1) / GBM, CDIM / GBN), GTHR, GSMEM_TOTAL, s2>>>(
        kvw, gw + NW, bk, kbuf, nullptr, NKV);
    gemm_tc<<<dim3((NKV + GBM - 1) / GBM, CDIM / GBN), GTHR, GSMEM_TOTAL, s2>>>(
        kvw, gw + 2 * NW, bv, vbuf, nullptr, NKV);
    k_rmsrope_kernel<<<NKV, 256, 0, s2>>>(gkw, kvf);
    cudaEventRecord(evJoin, s2);

    // ---- branch A (main stream): heat -> Q GEMM -> Q rms+rope ----
    heat_kernel<<<L1T, 256>>>(qh, te, mod, Wh, bh);          // g_heat + fp16 qh -> bufh
    gemm_tc<<<dim3((L1T + GBM - 1) / GBM, CDIM / GBN), GTHR, GSMEM_TOTAL>>>(
        bufh, gw, bq, nullptr, qhbuf, L1T);                  // Q proj -> fp16 g_qh
    q_rmsrope_kernel<<<L1T, 256>>>(gqw, qf);                 // in-place fp16

    // join, then attention + output GEMM
    cudaStreamWaitEvent(0, evJoin, 0);
    attn_kernel<<<dim3((HWD + 63) / 64, NH, T_FR), 256>>>(); // fp16 attn-out -> bufh
    gemm_tc<<<dim3((L1T + GBM - 1) / GBM, CDIM / GBN), GTHR, GSMEM_TOTAL>>>(
        bufh, gw + 3 * NW, bo, out, nullptr, L1T);
}